// round 9
// baseline (speedup 1.0000x reference)
#include <cuda_runtime.h>
#include <cuda_fp16.h>
#include <stdint.h>
#include <math.h>

namespace fv {
constexpr int C_ = 544, CIN_ = 1088, BT_ = 1024, P4_ = 4096, P16_ = 16384, PCH_ = 34;

// fp32 scratch (elements)
constexpr size_t OF_F    = 0;                              // [P4][544]
constexpr size_t OF_P2   = OF_F    + (size_t)P4_*C_;
constexpr size_t OF_WPT  = OF_P2   + (size_t)P4_*PCH_;
constexpr size_t OF_PP   = OF_WPT  + (size_t)PCH_*CIN_;
constexpr size_t OF_AB   = OF_PP   + (size_t)P4_*CIN_;     // [P4][2176]
constexpr size_t OF_AG   = OF_AB   + (size_t)P4_*2176;     // [P16][544]
constexpr size_t OF_FST  = OF_AG   + (size_t)P16_*C_;      // [P4][1088]
constexpr size_t OF_ATTL = OF_FST  + (size_t)P4_*CIN_;
constexpr size_t OF_ATTS = OF_ATTL + (size_t)P16_;
constexpr size_t OF_SBN  = OF_ATTS + (size_t)P16_;         // [5][2][1088]
constexpr size_t OF_RSWE = OF_SBN  + (size_t)5*2*CIN_;     // 2176
constexpr size_t OF_RSW1 = OF_RSWE + 2176;
constexpr size_t OF_RSW2 = OF_RSW1 + 1152;
constexpr size_t OF_RSAG = OF_RSW2 + 1152;
constexpr size_t OF_RSAT = OF_RSAG + 1152;
constexpr size_t OF_RSWS = OF_RSAT + 1152;                 // 640
constexpr size_t OF_RS01 = OF_RSWS + 640;                  // 1152
constexpr size_t TOT_F32 = OF_RS01 + 1152;

// fp16 row-major scratch [rows][K]
constexpr size_t SZ_FB  = (size_t)P4_ * C_;
constexpr size_t SZ_H   = (size_t)P16_ * CIN_;
constexpr size_t SZ_WE  = (size_t)2176 * 544;
constexpr size_t SZ_WB  = (size_t)1152 * 1088;
constexpr size_t SZ_WS  = (size_t)640 * 1088;
constexpr size_t SZ_W01 = (size_t)1152 * 544;

constexpr size_t OB_FB   = 0;
constexpr size_t OB_H0   = OB_FB   + SZ_FB;
constexpr size_t OB_H1   = OB_H0   + SZ_H;
constexpr size_t OB_H2   = OB_H1   + SZ_H;
constexpr size_t OB_G    = OB_H2   + SZ_H;
constexpr size_t OB_WEH  = OB_G    + SZ_H;
constexpr size_t OB_WEL  = OB_WEH  + SZ_WE;
constexpr size_t OB_W1H  = OB_WEL  + SZ_WE;
constexpr size_t OB_W1L  = OB_W1H  + SZ_WB;
constexpr size_t OB_W2H  = OB_W1L  + SZ_WB;
constexpr size_t OB_W2L  = OB_W2H  + SZ_WB;
constexpr size_t OB_WAGH = OB_W2L  + SZ_WB;
constexpr size_t OB_WAGL = OB_WAGH + SZ_WB;
constexpr size_t OB_WATH = OB_WAGL + SZ_WB;
constexpr size_t OB_WATL = OB_WATH + SZ_WB;
constexpr size_t OB_WSH  = OB_WATL + SZ_WB;
constexpr size_t OB_WSL  = OB_WSH  + SZ_WS;
constexpr size_t OB_W01H = OB_WSL  + SZ_WS;
constexpr size_t OB_W01L = OB_W01H + SZ_W01;
constexpr size_t TOT_H16 = OB_W01L + SZ_W01;
}  // namespace fv

__device__ float  g_F32[fv::TOT_F32];
__device__ __half g_H16[fv::TOT_H16];

using namespace fv;

// ---------------- baseline-PTX helpers ----------------
__device__ __forceinline__ uint32_t smem_u32(const void* p) {
    uint32_t a;
    asm("{ .reg .u64 t; cvta.to.shared.u64 t, %1; cvt.u32.u64 %0, t; }" : "=r"(a) : "l"(p));
    return a;
}
__device__ __forceinline__ void cp16(uint32_t dst, const void* src) {
    asm volatile("cp.async.cg.shared.global [%0], [%1], 16;" :: "r"(dst), "l"(src));
}
#define CP_COMMIT() asm volatile("cp.async.commit_group;" ::: "memory")
#define CP_WAIT(n)  asm volatile("cp.async.wait_group %0;" :: "n"(n) : "memory")

__device__ __forceinline__ void ldsm_x4(uint32_t (&r)[4], uint32_t addr) {
    asm volatile("ldmatrix.sync.aligned.m8n8.x4.shared.b16 {%0,%1,%2,%3}, [%4];"
                 : "=r"(r[0]), "=r"(r[1]), "=r"(r[2]), "=r"(r[3]) : "r"(addr));
}
__device__ __forceinline__ void mma_f16(float (&d)[4], const uint32_t (&a)[4],
                                        const uint32_t (&b)[2]) {
    asm volatile(
        "mma.sync.aligned.m16n8k16.row.col.f32.f16.f16.f32 "
        "{%0,%1,%2,%3}, {%4,%5,%6,%7}, {%8,%9}, {%0,%1,%2,%3};"
        : "+f"(d[0]), "+f"(d[1]), "+f"(d[2]), "+f"(d[3])
        : "r"(a[0]), "r"(a[1]), "r"(a[2]), "r"(a[3]), "r"(b[0]), "r"(b[1]));
}

// ---------------- prep / elementwise ----------------
__global__ void k_bn_fold(const float* __restrict__ b0, const float* __restrict__ b1,
                          const float* __restrict__ b2, const float* __restrict__ b3,
                          const float* __restrict__ b4, float* __restrict__ sbn) {
    int idx = blockIdx.x * blockDim.x + threadIdx.x;
    if (idx >= 5 * CIN_) return;
    int w = idx / CIN_, c = idx % CIN_;
    const float* bn = w == 0 ? b0 : w == 1 ? b1 : w == 2 ? b2 : w == 3 ? b3 : b4;
    float s = bn[c] * rsqrtf(bn[3 * CIN_ + c] + 1e-5f);
    sbn[w * 2 * CIN_ + c] = s;
    sbn[w * 2 * CIN_ + CIN_ + c] = bn[CIN_ + c] - bn[2 * CIN_ + c] * s;
}

__global__ void k_wposT(const float* __restrict__ wpos, float* __restrict__ wpt) {
    int idx = blockIdx.x * blockDim.x + threadIdx.x;
    if (idx >= PCH_ * CIN_) return;
    int k = idx / CIN_, o = idx % CIN_;
    wpt[idx] = wpos[o * PCH_ + k];
}

// weight addressing modes:
// 0: src[r*ld + k]
// 2: stacked Wsm^T: src[(r/544)*295936 + k*544 + (r%544)]
// 3: stacked We:    src[(r%1088)*1088 + (r/1088)*544 + k]
__device__ __forceinline__ float wsrc(const float* src, int ld, int mode, int r, int k) {
    if (mode == 0) return src[(size_t)r * ld + k];
    if (mode == 2) return src[(size_t)(r / 544) * 295936 + (size_t)k * 544 + (r % 544)];
    return src[(size_t)(r % 1088) * 1088 + (size_t)(r / 1088) * 544 + k];
}

__global__ void k_wscale(const float* __restrict__ src, int ld, int Msrc, int K,
                         int MP, int mode, float* __restrict__ rs) {
    int w = threadIdx.x >> 5, lane = threadIdx.x & 31;
    int r = blockIdx.x * 8 + w;
    if (r >= MP) return;
    float mx = 0.f;
    if (r < Msrc)
        for (int k = lane; k < K; k += 32) mx = fmaxf(mx, fabsf(wsrc(src, ld, mode, r, k)));
#pragma unroll
    for (int o = 16; o > 0; o >>= 1) mx = fmaxf(mx, __shfl_xor_sync(0xFFFFFFFFu, mx, o));
    if (lane == 0) {
        int e = 0;
        if (mx > 0.f) frexpf(mx, &e);
        rs[r] = exp2f((float)e);
    }
}

__global__ void k_wprep(const float* __restrict__ src, int ld, int Msrc, int K,
                        int MP, int mode, const float* __restrict__ rs,
                        __half* __restrict__ hi, __half* __restrict__ lo) {
    int K8 = K >> 3;
    int idx = blockIdx.x * blockDim.x + threadIdx.x;
    if (idx >= MP * K8) return;
    int r = idx / K8, k0 = (idx % K8) * 8;
    float inv = 1.0f / rs[r];
    union { __half h[8]; uint4 v; } ph, pl;
#pragma unroll
    for (int e = 0; e < 8; e++) {
        float x = (r < Msrc) ? wsrc(src, ld, mode, r, k0 + e) * inv : 0.f;
        __half h = __float2half(x);
        ph.h[e] = h;
        pl.h[e] = __float2half(x - __half2float(h));
    }
    size_t o = (size_t)r * K + k0;
    *reinterpret_cast<uint4*>(hi + o) = ph.v;
    *reinterpret_cast<uint4*>(lo + o) = pl.v;
}

__global__ void k_build_f(const float* __restrict__ x, float* __restrict__ F,
                          __half* __restrict__ fb) {
    int idx = blockIdx.x * blockDim.x + threadIdx.x;
    if (idx >= P4_ * 68) return;
    int p = idx / 68, c0 = (idx % 68) * 8;
    int bt = p >> 2, n = p & 3;
    union { __half h[8]; uint4 v; } ph;
    float vv[8];
#pragma unroll
    for (int e = 0; e < 8; e++) {
        vv[e] = x[((size_t)bt * C_ + c0 + e) * 4 + n];
        ph.h[e] = __float2half(vv[e]);
    }
    size_t o = (size_t)p * C_ + c0;
    *reinterpret_cast<uint4*>(fb + o) = ph.v;
    float4* d = reinterpret_cast<float4*>(F + o);
    d[0] = make_float4(vv[0], vv[1], vv[2], vv[3]);
    d[1] = make_float4(vv[4], vv[5], vv[6], vv[7]);
}

__global__ void k_build_p(const float* __restrict__ pos, float* __restrict__ P2) {
    int idx = blockIdx.x * blockDim.x + threadIdx.x;
    if (idx >= P4_ * PCH_) return;
    int p = idx / PCH_, k = idx % PCH_;
    P2[idx] = pos[((size_t)(p >> 2) * PCH_ + k) * 4 + (p & 3)];
}

__global__ void k_pos(const float* __restrict__ wpt, const float* __restrict__ P2,
                      float* __restrict__ PP) {
    int idx = blockIdx.x * blockDim.x + threadIdx.x;
    if (idx >= P4_ * CIN_) return;
    int p = idx / CIN_, o = idx % CIN_;
    float acc = 0.f;
#pragma unroll
    for (int k = 0; k < PCH_; k++) acc = fmaf(wpt[k * CIN_ + o], P2[p * PCH_ + k], acc);
    PP[idx] = acc;
}

__global__ void k_h0(const float* __restrict__ AB, const float* __restrict__ PP,
                     const float* __restrict__ bpos, const float* __restrict__ sbn,
                     __half* __restrict__ hh) {
    int idx = blockIdx.x * blockDim.x + threadIdx.x;
    if (idx >= P16_ * 136) return;
    int p16 = idx / 136, o0 = (idx % 136) * 8;
    int bt = p16 >> 4, ij = p16 & 15, i = ij >> 2, j = ij & 3;
    size_t pa = (size_t)(bt * 4 + i) * 2176 + o0;
    size_t pb = (size_t)(bt * 4 + j) * 2176 + 1088 + o0;
    size_t qi = (size_t)(bt * 4 + i) * CIN_ + o0;
    size_t qj = (size_t)(bt * 4 + j) * CIN_ + o0;
    union { __half h[8]; uint4 v; } ph;
#pragma unroll
    for (int e = 0; e < 8; e++) {
        int o = o0 + e;
        float v = fmaxf(fmaf(sbn[o], AB[pa + e] + AB[pb + e], sbn[CIN_ + o]), 0.f);
        v += PP[qi + e] - PP[qj + e] + bpos[o];
        ph.h[e] = __float2half(v);
    }
    *reinterpret_cast<uint4*>(hh + (size_t)p16 * CIN_ + o0) = ph.v;
}

__global__ void k_attl_init(const float* __restrict__ b, float* __restrict__ L) {
    int p = blockIdx.x * blockDim.x + threadIdx.x;
    if (p < P16_) L[p] = b[0];
}

__global__ void k_softmax(const float* __restrict__ L, float* __restrict__ S) {
    int r = blockIdx.x * blockDim.x + threadIdx.x;
    if (r >= P4_) return;
    float l0 = L[r*4], l1 = L[r*4+1], l2 = L[r*4+2], l3 = L[r*4+3];
    float m = fmaxf(fmaxf(l0, l1), fmaxf(l2, l3));
    float e0 = __expf(l0-m), e1 = __expf(l1-m), e2 = __expf(l2-m), e3 = __expf(l3-m);
    float inv = 1.f / (e0+e1+e2+e3);
    S[r*4]=e0*inv; S[r*4+1]=e1*inv; S[r*4+2]=e2*inv; S[r*4+3]=e3*inv;
}

__global__ void k_fuse(const float* __restrict__ F, const float* __restrict__ FST,
                       const float* __restrict__ AG, const float* __restrict__ S,
                       float* __restrict__ out) {
    int idx = blockIdx.x * blockDim.x + threadIdx.x;
    if (idx >= BT_ * 2176) return;
    int bt = idx / 2176, rem = idx % 2176;
    int i = rem / C_, d = rem % C_;
    int ri = bt * 4 + i;
    float acc = F[(size_t)ri * C_ + d];
#pragma unroll
    for (int j = 0; j < 4; j++) {
        float a = S[ri * 4 + j];
        if (j == i) acc = fmaf(FST[(size_t)ri * CIN_ + d], a, acc);
        else acc = fmaf(FST[(size_t)(bt*4+j) * CIN_ + 544 + d] *
                        AG[(size_t)(bt*16+i*4+j) * C_ + d], a, acc);
    }
    out[(size_t)bt * 2176 + d * 4 + i] = acc;
}

// ---------------- HMMA fp16 2-pass GEMM (128x64 tile, 3 CTAs/SM) ----------------
// C[m][n] = (Ah+Al)[MP][K] @ B[NP][K]^T, per-row scale rs applied in epilogue.
// EPI: 0 v*rs fp32 | 2 relu->fp16 | 3 fp16resid+relu->fp16 | 4 v*rs+bias fp32 | 5 att-dot atomic
constexpr int TILA = 8192;                 // 128 rows x 64 B
constexpr int TILB = 4096;                 // 64 rows x 64 B
constexpr int STG  = 2 * TILA + TILB;      // Ah|Al|B = 20 KB
constexpr int SMEMB = 3 * STG;             // 60 KB, 3 stages -> 3 CTAs/SM

__device__ __forceinline__ uint32_t swadr(uint32_t base, int row, int c16) {
    return base + row * 64 + ((c16 ^ ((row >> 1) & 3)) << 4);
}

template <int EPI>
__global__ void __launch_bounds__(256, 3)
gemm_mma(const __half* __restrict__ Ahg, const __half* __restrict__ Alg,
         const __half* __restrict__ Bg,
         int K, int KB, int Mreal,
         float* __restrict__ outf, int ldo,
         __half* __restrict__ oh, int ldob,
         const float* __restrict__ sv, const float* __restrict__ tv,
         const float* __restrict__ rs,
         const __half* __restrict__ r16,
         const float* __restrict__ watt) {
    extern __shared__ __half smbuf[];
    const uint32_t sb = smem_u32(smbuf);
    const int tid = threadIdx.x, lane = tid & 31, wid = tid >> 5;
    const int mt = blockIdx.x, nt = blockIdx.y;
    // 4x2 warp grid over 128x64: warp tile 32 (M) x 32 (N)
    const int wm = (wid & 3) * 32, wn = (wid >> 2) * 32;

    float acc[2][4][4];
#pragma unroll
    for (int a = 0; a < 2; a++)
#pragma unroll
        for (int b = 0; b < 4; b++)
#pragma unroll
            for (int c = 0; c < 4; c++) acc[a][b][c] = 0.f;

    auto load_stage = [&](int s, int kb) {
        uint32_t dstb = sb + s * STG;
        int k0 = kb * 32;
#pragma unroll
        for (int c = 0; c < 2; c++) {
            int q = tid + c * 256;
            int r = q >> 2, ch = q & 3;
            uint32_t d = dstb + r * 64 + ((ch ^ ((r >> 1) & 3)) << 4);
            size_t offA = (size_t)(mt * 128 + r) * K + k0 + ch * 8;
            cp16(d,        Ahg + offA);
            cp16(d + TILA, Alg + offA);
        }
        {
            int r = tid >> 2, ch = tid & 3;
            uint32_t d = dstb + 2 * TILA + r * 64 + ((ch ^ ((r >> 1) & 3)) << 4);
            size_t offB = (size_t)(nt * 64 + r) * K + k0 + ch * 8;
            cp16(d, Bg + offB);
        }
    };

    const int grp = lane >> 3, lrow = lane & 7;

    auto compute_stage = [&](int s) {
        uint32_t base = sb + s * STG;
#pragma unroll
        for (int ks2 = 0; ks2 < 2; ks2++) {
            uint32_t ah[2][4], al[2][4], bf[4][2];
            const int cA = ks2 * 2 + (grp >> 1);
            const int cB = ks2 * 2 + (grp & 1);
#pragma unroll
            for (int mi = 0; mi < 2; mi++) {
                int row = wm + mi * 16 + (grp & 1) * 8 + lrow;
                ldsm_x4(ah[mi], swadr(base, row, cA));
                ldsm_x4(al[mi], swadr(base + TILA, row, cA));
            }
#pragma unroll
            for (int n2 = 0; n2 < 2; n2++) {
                int row = wn + n2 * 16 + (grp >> 1) * 8 + lrow;
                uint32_t q[4];
                ldsm_x4(q, swadr(base + 2 * TILA, row, cB));
                bf[n2 * 2][0] = q[0]; bf[n2 * 2][1] = q[1];
                bf[n2 * 2 + 1][0] = q[2]; bf[n2 * 2 + 1][1] = q[3];
            }
#pragma unroll
            for (int mi = 0; mi < 2; mi++)
#pragma unroll
                for (int ni = 0; ni < 4; ni++) mma_f16(acc[mi][ni], ah[mi], bf[ni]);
#pragma unroll
            for (int mi = 0; mi < 2; mi++)
#pragma unroll
                for (int ni = 0; ni < 4; ni++) mma_f16(acc[mi][ni], al[mi], bf[ni]);
        }
    };

    load_stage(0, 0); CP_COMMIT();
    if (KB > 1) { load_stage(1, 1); CP_COMMIT(); }
    for (int kb = 0; kb < KB; kb++) {
        if (kb + 1 < KB) { CP_WAIT(1); } else { CP_WAIT(0); }
        __syncthreads();
        if (kb + 2 < KB) { load_stage((kb + 2) % 3, kb + 2); CP_COMMIT(); }
        compute_stage(kb % 3);
    }
    __syncthreads();

    // transpose through smem: Cs[n (64)][m (128 + pad 4)]
    float* Cs = reinterpret_cast<float*>(smbuf);
#pragma unroll
    for (int mi = 0; mi < 2; mi++)
#pragma unroll
        for (int ni = 0; ni < 4; ni++) {
            int rm = wm + mi * 16 + (lane >> 2);
            int cn = wn + ni * 8 + 2 * (lane & 3);
            Cs[cn * 132 + rm]           = acc[mi][ni][0];
            Cs[(cn + 1) * 132 + rm]     = acc[mi][ni][1];
            Cs[cn * 132 + rm + 8]       = acc[mi][ni][2];
            Cs[(cn + 1) * 132 + rm + 8] = acc[mi][ni][3];
        }
    __syncthreads();

    {
        int nl = tid >> 2, m0 = (tid & 3) * 32;
        int ng = nt * 64 + nl;
        int mg0 = mt * 128 + m0;
        if constexpr (EPI == 5) {
            float wsum = 0.f;
#pragma unroll 8
            for (int j = 0; j < 32; j++) {
                int m = mg0 + j;
                if (m >= Mreal) break;
                float v = Cs[nl * 132 + m0 + j] * rs[m];
                wsum = fmaf(fmaxf(fmaf(sv[m], v, tv[m]), 0.f), watt[m], wsum);
            }
            atomicAdd(&outf[ng], wsum);
        } else if constexpr (EPI == 2 || EPI == 3) {
#pragma unroll
            for (int j0 = 0; j0 < 32; j0 += 8) {
                if (mg0 + j0 >= Mreal) break;
                union { __half h[8]; uint4 v; } ph;
                float rv[8];
                if constexpr (EPI == 3) {
                    uint4 r4 = *reinterpret_cast<const uint4*>(r16 + (size_t)ng * ldob + mg0 + j0);
                    const __half* rr = reinterpret_cast<const __half*>(&r4);
#pragma unroll
                    for (int e = 0; e < 8; e++) rv[e] = __half2float(rr[e]);
                }
#pragma unroll
                for (int e = 0; e < 8; e++) {
                    int m = mg0 + j0 + e;
                    float v = Cs[nl * 132 + m0 + j0 + e] * rs[m];
                    float w = fmaxf(fmaf(sv[m], v, tv[m]), 0.f);
                    if constexpr (EPI == 3) w += rv[e];
                    ph.h[e] = __float2half(w);
                }
                *reinterpret_cast<uint4*>(oh + (size_t)ng * ldob + mg0 + j0) = ph.v;
            }
        } else {
#pragma unroll
            for (int j0 = 0; j0 < 32; j0 += 4) {
                if (mg0 + j0 >= Mreal) break;
                float4 ov;
                float* pv = reinterpret_cast<float*>(&ov);
#pragma unroll
                for (int e = 0; e < 4; e++) {
                    int m = mg0 + j0 + e;
                    float v = Cs[nl * 132 + m0 + j0 + e] * rs[m];
                    if constexpr (EPI == 4) v = v + sv[m];
                    pv[e] = v;
                }
                *reinterpret_cast<float4*>(outf + (size_t)ng * ldo + mg0 + j0) = ov;
            }
        }
    }
}

// ---------------- launch ----------------
extern "C" void kernel_launch(void* const* d_in, const int* in_sizes, int n_in,
                              void* d_out, int out_size) {
    const float *x = (const float*)d_in[0], *pos2d = (const float*)d_in[1];
    const float *w_pos = (const float*)d_in[2], *b_pos = (const float*)d_in[3];
    const float *w_e = (const float*)d_in[4],  *w1 = (const float*)d_in[6];
    const float *w2 = (const float*)d_in[8],   *w_ag = (const float*)d_in[10];
    const float *w_ag_s = (const float*)d_in[12], *b_ag_s = (const float*)d_in[13];
    const float *w_att = (const float*)d_in[14], *w_att_s = (const float*)d_in[16];
    const float *b_att_s = (const float*)d_in[17], *Wsm = (const float*)d_in[18];
    float* out = (float*)d_out;

    float* F32 = nullptr;  __half* H16 = nullptr;
    cudaGetSymbolAddress((void**)&F32, g_F32);
    cudaGetSymbolAddress((void**)&H16, g_H16);

    float *F = F32+OF_F, *P2 = F32+OF_P2, *WPT = F32+OF_WPT, *PP = F32+OF_PP;
    float *AB = F32+OF_AB, *AG = F32+OF_AG, *FST = F32+OF_FST;
    float *ATTL = F32+OF_ATTL, *ATTS = F32+OF_ATTS, *SBN = F32+OF_SBN;
    float *RSWE = F32+OF_RSWE, *RSW1 = F32+OF_RSW1, *RSW2 = F32+OF_RSW2;
    float *RSAG = F32+OF_RSAG, *RSAT = F32+OF_RSAT, *RSWS = F32+OF_RSWS, *RS01 = F32+OF_RS01;

    cudaFuncSetAttribute(gemm_mma<0>, cudaFuncAttributeMaxDynamicSharedMemorySize, SMEMB);
    cudaFuncSetAttribute(gemm_mma<2>, cudaFuncAttributeMaxDynamicSharedMemorySize, SMEMB);
    cudaFuncSetAttribute(gemm_mma<3>, cudaFuncAttributeMaxDynamicSharedMemorySize, SMEMB);
    cudaFuncSetAttribute(gemm_mma<4>, cudaFuncAttributeMaxDynamicSharedMemorySize, SMEMB);
    cudaFuncSetAttribute(gemm_mma<5>, cudaFuncAttributeMaxDynamicSharedMemorySize, SMEMB);

    // launches 1-3, then the big layer-1 GEMM at slot 4 (ncu captures the 4th launch)
    k_build_f<<<(P4_*68+255)/256, 256>>>(x, F, H16+OB_FB);
    k_wscale<<<(2176+7)/8, 256>>>(w_e, 0, 2176, 544, 2176, 3, RSWE);
    k_wprep<<<(2176*68+255)/256, 256>>>(w_e, 0, 2176, 544, 2176, 3, RSWE, H16+OB_WEH, H16+OB_WEL);
    gemm_mma<0><<<dim3(17,64),256,SMEMB>>>(H16+OB_WEH, H16+OB_WEL, H16+OB_FB,
                                           544, 17, 2176, AB, 2176, nullptr, 0,
                                           nullptr, nullptr, RSWE, nullptr, nullptr);

    k_bn_fold<<<(5*CIN_+255)/256, 256>>>((const float*)d_in[5], (const float*)d_in[7],
                                         (const float*)d_in[9], (const float*)d_in[11],
                                         (const float*)d_in[15], SBN);
    k_wposT<<<(PCH_*CIN_+255)/256, 256>>>(w_pos, WPT);
    k_build_p<<<(P4_*PCH_+255)/256, 256>>>(pos2d, P2);
    k_pos<<<(P4_*CIN_+255)/256, 256>>>(WPT, P2, PP);
    k_h0<<<(P16_*136+255)/256, 256>>>(AB, PP, b_pos, SBN, H16+OB_H0);

    // weight preps
    k_wscale<<<(1152+7)/8, 256>>>(w1,    CIN_, 1088, 1088, 1152, 0, RSW1);
    k_wprep<<<(1152*136+255)/256, 256>>>(w1,    CIN_, 1088, 1088, 1152, 0, RSW1, H16+OB_W1H,  H16+OB_W1L);
    k_wscale<<<(1152+7)/8, 256>>>(w2,    CIN_, 1088, 1088, 1152, 0, RSW2);
    k_wprep<<<(1152*136+255)/256, 256>>>(w2,    CIN_, 1088, 1088, 1152, 0, RSW2, H16+OB_W2H,  H16+OB_W2L);
    k_wscale<<<(1152+7)/8, 256>>>(w_ag,  CIN_, 1088, 1088, 1152, 0, RSAG);
    k_wprep<<<(1152*136+255)/256, 256>>>(w_ag,  CIN_, 1088, 1088, 1152, 0, RSAG, H16+OB_WAGH, H16+OB_WAGL);
    k_wscale<<<(1152+7)/8, 256>>>(w_att, CIN_, 1088, 1088, 1152, 0, RSAT);
    k_wprep<<<(1152*136+255)/256, 256>>>(w_att, CIN_, 1088, 1088, 1152, 0, RSAT, H16+OB_WATH, H16+OB_WATL);
    k_wscale<<<(640+7)/8, 256>>>(w_ag_s, CIN_, 544, 1088, 640, 0, RSWS);
    k_wprep<<<(640*136+255)/256, 256>>>(w_ag_s, CIN_, 544, 1088, 640, 0, RSWS, H16+OB_WSH, H16+OB_WSL);
    k_wscale<<<(1152+7)/8, 256>>>(Wsm, 0, 1088, 544, 1152, 2, RS01);
    k_wprep<<<(1152*68+255)/256, 256>>>(Wsm, 0, 1088, 544, 1152, 2, RS01, H16+OB_W01H, H16+OB_W01L);

    // trunk
    gemm_mma<2><<<dim3(9,256),256,SMEMB>>>(H16+OB_W1H, H16+OB_W1L, H16+OB_H0,
                                           1088, 34, 1088, nullptr, 0, H16+OB_H1, CIN_,
                                           SBN+2*CIN_, SBN+3*CIN_, RSW1, nullptr, nullptr);
    gemm_mma<3><<<dim3(9,256),256,SMEMB>>>(H16+OB_W2H, H16+OB_W2L, H16+OB_H1,
                                           1088, 34, 1088, nullptr, 0, H16+OB_H2, CIN_,
                                           SBN+4*CIN_, SBN+5*CIN_, RSW2, H16+OB_H0, nullptr);
    // aggregation branch
    gemm_mma<2><<<dim3(9,256),256,SMEMB>>>(H16+OB_WAGH, H16+OB_WAGL, H16+OB_H2,
                                           1088, 34, 1088, nullptr, 0, H16+OB_G, CIN_,
                                           SBN+6*CIN_, SBN+7*CIN_, RSAG, nullptr, nullptr);
    gemm_mma<4><<<dim3(5,256),256,SMEMB>>>(H16+OB_WSH, H16+OB_WSL, H16+OB_G,
                                           1088, 34, 544, AG, C_, nullptr, 0,
                                           b_ag_s, nullptr, RSWS, nullptr, nullptr);
    // attention branch: logits fused into GEMM epilogue
    k_attl_init<<<(P16_+255)/256, 256>>>(b_att_s, ATTL);
    gemm_mma<5><<<dim3(9,256),256,SMEMB>>>(H16+OB_WATH, H16+OB_WATL, H16+OB_H2,
                                           1088, 34, 1088, ATTL, 0, nullptr, 0,
                                           SBN+8*CIN_, SBN+9*CIN_, RSAT, nullptr, w_att_s);
    k_softmax<<<(P4_+255)/256, 256>>>(ATTL, ATTS);

    // self/transfer stacked: FST = [W0^T; W1^T] @ f
    gemm_mma<0><<<dim3(9,64),256,SMEMB>>>(H16+OB_W01H, H16+OB_W01L, H16+OB_FB,
                                          544, 17, 1088, FST, CIN_, nullptr, 0,
                                          nullptr, nullptr, RS01, nullptr, nullptr);

    k_fuse<<<(BT_*2176+255)/256, 256>>>(F, FST, AG, ATTS, out);
}

// round 10
// speedup vs baseline: 1.5263x; 1.5263x over previous
#include <cuda_runtime.h>
#include <cuda_fp16.h>
#include <stdint.h>
#include <math.h>

namespace fv {
constexpr int C_ = 544, CIN_ = 1088, BT_ = 1024, P4_ = 4096, P16_ = 16384, PCH_ = 34;

// fp32 scratch (elements)
constexpr size_t OF_F    = 0;                              // [P4][544]
constexpr size_t OF_P2   = OF_F    + (size_t)P4_*C_;
constexpr size_t OF_WPT  = OF_P2   + (size_t)P4_*PCH_;
constexpr size_t OF_PP   = OF_WPT  + (size_t)PCH_*CIN_;
constexpr size_t OF_AB   = OF_PP   + (size_t)P4_*CIN_;     // [P4][2176]
constexpr size_t OF_AG   = OF_AB   + (size_t)P4_*2176;     // [P16][544]
constexpr size_t OF_FST  = OF_AG   + (size_t)P16_*C_;      // [P4][1088]
constexpr size_t OF_ATTL = OF_FST  + (size_t)P4_*CIN_;
constexpr size_t OF_ATTS = OF_ATTL + (size_t)P16_;
constexpr size_t OF_SBN  = OF_ATTS + (size_t)P16_;         // [5][2][1088]
constexpr size_t OF_RSWE = OF_SBN  + (size_t)5*2*CIN_;     // 2176
constexpr size_t OF_RSW1 = OF_RSWE + 2176;
constexpr size_t OF_RSW2 = OF_RSW1 + 1152;
constexpr size_t OF_RSAG = OF_RSW2 + 1152;
constexpr size_t OF_RSAT = OF_RSAG + 1152;
constexpr size_t OF_RSWS = OF_RSAT + 1152;                 // 640
constexpr size_t OF_RS01 = OF_RSWS + 640;                  // 1152
constexpr size_t TOT_F32 = OF_RS01 + 1152;

// fp16 row-major scratch [rows][K]
constexpr size_t SZ_FB  = (size_t)P4_ * C_;
constexpr size_t SZ_H   = (size_t)P16_ * CIN_;
constexpr size_t SZ_WE  = (size_t)2176 * 544;
constexpr size_t SZ_WB  = (size_t)1152 * 1088;
constexpr size_t SZ_WS  = (size_t)640 * 1088;
constexpr size_t SZ_W01 = (size_t)1152 * 544;

constexpr size_t OB_FB   = 0;
constexpr size_t OB_H0   = OB_FB   + SZ_FB;
constexpr size_t OB_H1   = OB_H0   + SZ_H;
constexpr size_t OB_H2   = OB_H1   + SZ_H;
constexpr size_t OB_G    = OB_H2   + SZ_H;
constexpr size_t OB_WE   = OB_G    + SZ_H;
constexpr size_t OB_W1   = OB_WE   + SZ_WE;
constexpr size_t OB_W2   = OB_W1   + SZ_WB;
constexpr size_t OB_WAG  = OB_W2   + SZ_WB;
constexpr size_t OB_WAT  = OB_WAG  + SZ_WB;
constexpr size_t OB_WS   = OB_WAT  + SZ_WB;
constexpr size_t OB_W01  = OB_WS   + SZ_WS;
constexpr size_t TOT_H16 = OB_W01  + SZ_W01;
}  // namespace fv

__device__ float  g_F32[fv::TOT_F32];
__device__ __half g_H16[fv::TOT_H16];

using namespace fv;

// ---------------- baseline-PTX helpers ----------------
__device__ __forceinline__ uint32_t smem_u32(const void* p) {
    uint32_t a;
    asm("{ .reg .u64 t; cvta.to.shared.u64 t, %1; cvt.u32.u64 %0, t; }" : "=r"(a) : "l"(p));
    return a;
}
__device__ __forceinline__ void cp16(uint32_t dst, const void* src) {
    asm volatile("cp.async.cg.shared.global [%0], [%1], 16;" :: "r"(dst), "l"(src));
}
#define CP_COMMIT() asm volatile("cp.async.commit_group;" ::: "memory")
#define CP_WAIT(n)  asm volatile("cp.async.wait_group %0;" :: "n"(n) : "memory")

__device__ __forceinline__ void ldsm_x4(uint32_t (&r)[4], uint32_t addr) {
    asm volatile("ldmatrix.sync.aligned.m8n8.x4.shared.b16 {%0,%1,%2,%3}, [%4];"
                 : "=r"(r[0]), "=r"(r[1]), "=r"(r[2]), "=r"(r[3]) : "r"(addr));
}
__device__ __forceinline__ void mma_f16(float (&d)[4], const uint32_t (&a)[4],
                                        const uint32_t (&b)[2]) {
    asm volatile(
        "mma.sync.aligned.m16n8k16.row.col.f32.f16.f16.f32 "
        "{%0,%1,%2,%3}, {%4,%5,%6,%7}, {%8,%9}, {%0,%1,%2,%3};"
        : "+f"(d[0]), "+f"(d[1]), "+f"(d[2]), "+f"(d[3])
        : "r"(a[0]), "r"(a[1]), "r"(a[2]), "r"(a[3]), "r"(b[0]), "r"(b[1]));
}

// ---------------- prep / elementwise ----------------
__global__ void k_bn_fold(const float* __restrict__ b0, const float* __restrict__ b1,
                          const float* __restrict__ b2, const float* __restrict__ b3,
                          const float* __restrict__ b4, float* __restrict__ sbn) {
    int idx = blockIdx.x * blockDim.x + threadIdx.x;
    if (idx >= 5 * CIN_) return;
    int w = idx / CIN_, c = idx % CIN_;
    const float* bn = w == 0 ? b0 : w == 1 ? b1 : w == 2 ? b2 : w == 3 ? b3 : b4;
    float s = bn[c] * rsqrtf(bn[3 * CIN_ + c] + 1e-5f);
    sbn[w * 2 * CIN_ + c] = s;
    sbn[w * 2 * CIN_ + CIN_ + c] = bn[CIN_ + c] - bn[2 * CIN_ + c] * s;
}

__global__ void k_wposT(const float* __restrict__ wpos, float* __restrict__ wpt) {
    int idx = blockIdx.x * blockDim.x + threadIdx.x;
    if (idx >= PCH_ * CIN_) return;
    int k = idx / CIN_, o = idx % CIN_;
    wpt[idx] = wpos[o * PCH_ + k];
}

// weight addressing modes:
// 0: src[r*ld + k]
// 2: stacked Wsm^T: src[(r/544)*295936 + k*544 + (r%544)]
// 3: stacked We:    src[(r%1088)*1088 + (r/1088)*544 + k]
__device__ __forceinline__ float wsrc(const float* src, int ld, int mode, int r, int k) {
    if (mode == 0) return src[(size_t)r * ld + k];
    if (mode == 2) return src[(size_t)(r / 544) * 295936 + (size_t)k * 544 + (r % 544)];
    return src[(size_t)(r % 1088) * 1088 + (size_t)(r / 1088) * 544 + k];
}

__global__ void k_wscale(const float* __restrict__ src, int ld, int Msrc, int K,
                         int MP, int mode, float* __restrict__ rs) {
    int w = threadIdx.x >> 5, lane = threadIdx.x & 31;
    int r = blockIdx.x * 8 + w;
    if (r >= MP) return;
    float mx = 0.f;
    if (r < Msrc)
        for (int k = lane; k < K; k += 32) mx = fmaxf(mx, fabsf(wsrc(src, ld, mode, r, k)));
#pragma unroll
    for (int o = 16; o > 0; o >>= 1) mx = fmaxf(mx, __shfl_xor_sync(0xFFFFFFFFu, mx, o));
    if (lane == 0) {
        int e = 0;
        if (mx > 0.f) frexpf(mx, &e);
        rs[r] = exp2f((float)e);
    }
}

// weight -> padded row-major [MP][K] fp16 (single, row-scaled)
__global__ void k_wprep(const float* __restrict__ src, int ld, int Msrc, int K,
                        int MP, int mode, const float* __restrict__ rs,
                        __half* __restrict__ hi) {
    int K8 = K >> 3;
    int idx = blockIdx.x * blockDim.x + threadIdx.x;
    if (idx >= MP * K8) return;
    int r = idx / K8, k0 = (idx % K8) * 8;
    float inv = 1.0f / rs[r];
    union { __half h[8]; uint4 v; } ph;
#pragma unroll
    for (int e = 0; e < 8; e++) {
        float x = (r < Msrc) ? wsrc(src, ld, mode, r, k0 + e) * inv : 0.f;
        ph.h[e] = __float2half(x);
    }
    *reinterpret_cast<uint4*>(hi + (size_t)r * K + k0) = ph.v;
}

__global__ void k_build_f(const float* __restrict__ x, float* __restrict__ F,
                          __half* __restrict__ fb) {
    int idx = blockIdx.x * blockDim.x + threadIdx.x;
    if (idx >= P4_ * 68) return;
    int p = idx / 68, c0 = (idx % 68) * 8;
    int bt = p >> 2, n = p & 3;
    union { __half h[8]; uint4 v; } ph;
    float vv[8];
#pragma unroll
    for (int e = 0; e < 8; e++) {
        vv[e] = x[((size_t)bt * C_ + c0 + e) * 4 + n];
        ph.h[e] = __float2half(vv[e]);
    }
    size_t o = (size_t)p * C_ + c0;
    *reinterpret_cast<uint4*>(fb + o) = ph.v;
    float4* d = reinterpret_cast<float4*>(F + o);
    d[0] = make_float4(vv[0], vv[1], vv[2], vv[3]);
    d[1] = make_float4(vv[4], vv[5], vv[6], vv[7]);
}

__global__ void k_build_p(const float* __restrict__ pos, float* __restrict__ P2) {
    int idx = blockIdx.x * blockDim.x + threadIdx.x;
    if (idx >= P4_ * PCH_) return;
    int p = idx / PCH_, k = idx % PCH_;
    P2[idx] = pos[((size_t)(p >> 2) * PCH_ + k) * 4 + (p & 3)];
}

__global__ void k_pos(const float* __restrict__ wpt, const float* __restrict__ P2,
                      float* __restrict__ PP) {
    int idx = blockIdx.x * blockDim.x + threadIdx.x;
    if (idx >= P4_ * CIN_) return;
    int p = idx / CIN_, o = idx % CIN_;
    float acc = 0.f;
#pragma unroll
    for (int k = 0; k < PCH_; k++) acc = fmaf(wpt[k * CIN_ + o], P2[p * PCH_ + k], acc);
    PP[idx] = acc;
}

__global__ void k_h0(const float* __restrict__ AB, const float* __restrict__ PP,
                     const float* __restrict__ bpos, const float* __restrict__ sbn,
                     __half* __restrict__ hh) {
    int idx = blockIdx.x * blockDim.x + threadIdx.x;
    if (idx >= P16_ * 136) return;
    int p16 = idx / 136, o0 = (idx % 136) * 8;
    int bt = p16 >> 4, ij = p16 & 15, i = ij >> 2, j = ij & 3;
    size_t pa = (size_t)(bt * 4 + i) * 2176 + o0;
    size_t pb = (size_t)(bt * 4 + j) * 2176 + 1088 + o0;
    size_t qi = (size_t)(bt * 4 + i) * CIN_ + o0;
    size_t qj = (size_t)(bt * 4 + j) * CIN_ + o0;
    union { __half h[8]; uint4 v; } ph;
#pragma unroll
    for (int e = 0; e < 8; e++) {
        int o = o0 + e;
        float v = fmaxf(fmaf(sbn[o], AB[pa + e] + AB[pb + e], sbn[CIN_ + o]), 0.f);
        v += PP[qi + e] - PP[qj + e] + bpos[o];
        ph.h[e] = __float2half(v);
    }
    *reinterpret_cast<uint4*>(hh + (size_t)p16 * CIN_ + o0) = ph.v;
}

__global__ void k_attl_init(const float* __restrict__ b, float* __restrict__ L) {
    int p = blockIdx.x * blockDim.x + threadIdx.x;
    if (p < P16_) L[p] = b[0];
}

__global__ void k_softmax(const float* __restrict__ L, float* __restrict__ S) {
    int r = blockIdx.x * blockDim.x + threadIdx.x;
    if (r >= P4_) return;
    float l0 = L[r*4], l1 = L[r*4+1], l2 = L[r*4+2], l3 = L[r*4+3];
    float m = fmaxf(fmaxf(l0, l1), fmaxf(l2, l3));
    float e0 = __expf(l0-m), e1 = __expf(l1-m), e2 = __expf(l2-m), e3 = __expf(l3-m);
    float inv = 1.f / (e0+e1+e2+e3);
    S[r*4]=e0*inv; S[r*4+1]=e1*inv; S[r*4+2]=e2*inv; S[r*4+3]=e3*inv;
}

__global__ void k_fuse(const float* __restrict__ F, const float* __restrict__ FST,
                       const float* __restrict__ AG, const float* __restrict__ S,
                       float* __restrict__ out) {
    int idx = blockIdx.x * blockDim.x + threadIdx.x;
    if (idx >= BT_ * 2176) return;
    int bt = idx / 2176, rem = idx % 2176;
    int i = rem / C_, d = rem % C_;
    int ri = bt * 4 + i;
    float acc = F[(size_t)ri * C_ + d];
#pragma unroll
    for (int j = 0; j < 4; j++) {
        float a = S[ri * 4 + j];
        if (j == i) acc = fmaf(FST[(size_t)ri * CIN_ + d], a, acc);
        else acc = fmaf(FST[(size_t)(bt*4+j) * CIN_ + 544 + d] *
                        AG[(size_t)(bt*16+i*4+j) * C_ + d], a, acc);
    }
    out[(size_t)bt * 2176 + d * 4 + i] = acc;
}

// ---------------- HMMA fp16 single-pass GEMM (128x128 tile, 4x2 warps) ----------------
// C[m][n] = A[MP][K] @ B[NP][K]^T, per-row scale rs applied in epilogue.
// EPI: 0 v*rs fp32 | 2 relu->fp16 | 3 fp16resid+relu->fp16 | 4 v*rs+bias fp32 | 5 att-dot atomic
constexpr int TIL = 8192;        // 128 rows x 64 B
constexpr int STG = 2 * TIL;     // A|B = 16 KB
constexpr int SMEMB = 67584;     // max(4 stages = 64 KB, Cs 128x132 f32 = 67.6 KB)

__device__ __forceinline__ uint32_t swadr(uint32_t base, int row, int c16) {
    return base + row * 64 + ((c16 ^ ((row >> 1) & 3)) << 4);
}

template <int EPI>
__global__ void __launch_bounds__(256, 2)
gemm_mma(const __half* __restrict__ Ag, const __half* __restrict__ Bg,
         int K, int KB, int Mreal,
         float* __restrict__ outf, int ldo,
         __half* __restrict__ oh, int ldob,
         const float* __restrict__ sv, const float* __restrict__ tv,
         const float* __restrict__ rs,
         const __half* __restrict__ r16,
         const float* __restrict__ watt) {
    extern __shared__ __half smbuf[];
    const uint32_t sb = smem_u32(smbuf);
    const int tid = threadIdx.x, lane = tid & 31, wid = tid >> 5;
    const int mt = blockIdx.x, nt = blockIdx.y;
    // 4x2 warp grid: warp tile 32 (M) x 64 (N)
    const int wm = (wid & 3) * 32, wn = (wid >> 2) * 64;

    float acc[2][8][4];
#pragma unroll
    for (int a = 0; a < 2; a++)
#pragma unroll
        for (int b = 0; b < 8; b++)
#pragma unroll
            for (int c = 0; c < 4; c++) acc[a][b][c] = 0.f;

    auto load_stage = [&](int s, int kb) {
        uint32_t dstb = sb + s * STG;
        int k0 = kb * 32;
#pragma unroll
        for (int c = 0; c < 2; c++) {
            int q = tid + c * 256;
            int r = q >> 2, ch = q & 3;
            uint32_t d = dstb + r * 64 + ((ch ^ ((r >> 1) & 3)) << 4);
            size_t offA = (size_t)(mt * 128 + r) * K + k0 + ch * 8;
            size_t offB = (size_t)(nt * 128 + r) * K + k0 + ch * 8;
            cp16(d,       Ag + offA);
            cp16(d + TIL, Bg + offB);
        }
    };

    const int grp = lane >> 3, lrow = lane & 7;

    auto compute_stage = [&](int s) {
        uint32_t base = sb + s * STG;
#pragma unroll
        for (int ks2 = 0; ks2 < 2; ks2++) {
            uint32_t ah[2][4], bf[8][2];
            const int cA = ks2 * 2 + (grp >> 1);
            const int cB = ks2 * 2 + (grp & 1);
#pragma unroll
            for (int mi = 0; mi < 2; mi++) {
                int row = wm + mi * 16 + (grp & 1) * 8 + lrow;
                ldsm_x4(ah[mi], swadr(base, row, cA));
            }
#pragma unroll
            for (int n2 = 0; n2 < 4; n2++) {
                int row = wn + n2 * 16 + (grp >> 1) * 8 + lrow;
                uint32_t q[4];
                ldsm_x4(q, swadr(base + TIL, row, cB));
                bf[n2 * 2][0] = q[0]; bf[n2 * 2][1] = q[1];
                bf[n2 * 2 + 1][0] = q[2]; bf[n2 * 2 + 1][1] = q[3];
            }
#pragma unroll
            for (int mi = 0; mi < 2; mi++)
#pragma unroll
                for (int ni = 0; ni < 8; ni++) mma_f16(acc[mi][ni], ah[mi], bf[ni]);
        }
    };

    load_stage(0, 0); CP_COMMIT();
    if (KB > 1) { load_stage(1, 1); CP_COMMIT(); }
    if (KB > 2) { load_stage(2, 2); CP_COMMIT(); }
    for (int kb = 0; kb < KB; kb++) {
        if (kb < KB - 2) { CP_WAIT(2); }
        else if (kb == KB - 2) { CP_WAIT(1); }
        else { CP_WAIT(0); }
        __syncthreads();
        if (kb + 3 < KB) { load_stage((kb + 3) & 3, kb + 3); CP_COMMIT(); }
        compute_stage(kb & 3);
    }
    __syncthreads();

    // transpose through smem: Cs[n (128)][m (128 + pad 4)]
    float* Cs = reinterpret_cast<float*>(smbuf);
#pragma unroll
    for (int mi = 0; mi < 2; mi++)
#pragma unroll
        for (int ni = 0; ni < 8; ni++) {
            int rm = wm + mi * 16 + (lane >> 2);
            int cn = wn + ni * 8 + 2 * (lane & 3);
            Cs[cn * 132 + rm]           = acc[mi][ni][0];
            Cs[(cn + 1) * 132 + rm]     = acc[mi][ni][1];
            Cs[cn * 132 + rm + 8]       = acc[mi][ni][2];
            Cs[(cn + 1) * 132 + rm + 8] = acc[mi][ni][3];
        }
    __syncthreads();

    {
        int nl = tid >> 1, m0 = (tid & 1) * 64;
        int ng = nt * 128 + nl;
        int mg0 = mt * 128 + m0;
        if constexpr (EPI == 5) {
            float wsum = 0.f;
#pragma unroll 8
            for (int j = 0; j < 64; j++) {
                int m = mg0 + j;
                if (m >= Mreal) break;
                float v = Cs[nl * 132 + m0 + j] * rs[m];
                wsum = fmaf(fmaxf(fmaf(sv[m], v, tv[m]), 0.f), watt[m], wsum);
            }
            atomicAdd(&outf[ng], wsum);
        } else if constexpr (EPI == 2 || EPI == 3) {
#pragma unroll
            for (int j0 = 0; j0 < 64; j0 += 8) {
                if (mg0 + j0 >= Mreal) break;
                union { __half h[8]; uint4 v; } ph;
                float rv[8];
                if constexpr (EPI == 3) {
                    uint4 r4 = *reinterpret_cast<const uint4*>(r16 + (size_t)ng * ldob + mg0 + j0);
                    const __half* rr = reinterpret_cast<const __half*>(&r4);
#pragma unroll
                    for (int e = 0; e < 8; e++) rv[e] = __half2float(rr[e]);
                }
#pragma unroll
                for (int e = 0; e < 8; e++) {
                    int m = mg0 + j0 + e;
                    float v = Cs[nl * 132 + m0 + j0 + e] * rs[m];
                    float w = fmaxf(fmaf(sv[m], v, tv[m]), 0.f);
                    if constexpr (EPI == 3) w += rv[e];
                    ph.h[e] = __float2half(w);
                }
                *reinterpret_cast<uint4*>(oh + (size_t)ng * ldob + mg0 + j0) = ph.v;
            }
        } else {
#pragma unroll
            for (int j0 = 0; j0 < 64; j0 += 4) {
                if (mg0 + j0 >= Mreal) break;
                float4 ov;
                float* pv = reinterpret_cast<float*>(&ov);
#pragma unroll
                for (int e = 0; e < 4; e++) {
                    int m = mg0 + j0 + e;
                    float v = Cs[nl * 132 + m0 + j0 + e] * rs[m];
                    if constexpr (EPI == 4) v = v + sv[m];
                    pv[e] = v;
                }
                *reinterpret_cast<float4*>(outf + (size_t)ng * ldo + mg0 + j0) = ov;
            }
        }
    }
}

// ---------------- launch ----------------
extern "C" void kernel_launch(void* const* d_in, const int* in_sizes, int n_in,
                              void* d_out, int out_size) {
    const float *x = (const float*)d_in[0], *pos2d = (const float*)d_in[1];
    const float *w_pos = (const float*)d_in[2], *b_pos = (const float*)d_in[3];
    const float *w_e = (const float*)d_in[4],  *w1 = (const float*)d_in[6];
    const float *w2 = (const float*)d_in[8],   *w_ag = (const float*)d_in[10];
    const float *w_ag_s = (const float*)d_in[12], *b_ag_s = (const float*)d_in[13];
    const float *w_att = (const float*)d_in[14], *w_att_s = (const float*)d_in[16];
    const float *b_att_s = (const float*)d_in[17], *Wsm = (const float*)d_in[18];
    float* out = (float*)d_out;

    float* F32 = nullptr;  __half* H16 = nullptr;
    cudaGetSymbolAddress((void**)&F32, g_F32);
    cudaGetSymbolAddress((void**)&H16, g_H16);

    float *F = F32+OF_F, *P2 = F32+OF_P2, *WPT = F32+OF_WPT, *PP = F32+OF_PP;
    float *AB = F32+OF_AB, *AG = F32+OF_AG, *FST = F32+OF_FST;
    float *ATTL = F32+OF_ATTL, *ATTS = F32+OF_ATTS, *SBN = F32+OF_SBN;
    float *RSWE = F32+OF_RSWE, *RSW1 = F32+OF_RSW1, *RSW2 = F32+OF_RSW2;
    float *RSAG = F32+OF_RSAG, *RSAT = F32+OF_RSAT, *RSWS = F32+OF_RSWS, *RS01 = F32+OF_RS01;

    cudaFuncSetAttribute(gemm_mma<0>, cudaFuncAttributeMaxDynamicSharedMemorySize, SMEMB);
    cudaFuncSetAttribute(gemm_mma<2>, cudaFuncAttributeMaxDynamicSharedMemorySize, SMEMB);
    cudaFuncSetAttribute(gemm_mma<3>, cudaFuncAttributeMaxDynamicSharedMemorySize, SMEMB);
    cudaFuncSetAttribute(gemm_mma<4>, cudaFuncAttributeMaxDynamicSharedMemorySize, SMEMB);
    cudaFuncSetAttribute(gemm_mma<5>, cudaFuncAttributeMaxDynamicSharedMemorySize, SMEMB);

    // launches 1-3, then the big layer-1 GEMM at slot 4 (ncu captures the 4th launch)
    k_build_f<<<(P4_*68+255)/256, 256>>>(x, F, H16+OB_FB);
    k_wscale<<<(2176+7)/8, 256>>>(w_e, 0, 2176, 544, 2176, 3, RSWE);
    k_wprep<<<(2176*68+255)/256, 256>>>(w_e, 0, 2176, 544, 2176, 3, RSWE, H16+OB_WE);
    gemm_mma<0><<<dim3(17,32),256,SMEMB>>>(H16+OB_WE, H16+OB_FB,
                                           544, 17, 2176, AB, 2176, nullptr, 0,
                                           nullptr, nullptr, RSWE, nullptr, nullptr);

    k_bn_fold<<<(5*CIN_+255)/256, 256>>>((const float*)d_in[5], (const float*)d_in[7],
                                         (const float*)d_in[9], (const float*)d_in[11],
                                         (const float*)d_in[15], SBN);
    k_wposT<<<(PCH_*CIN_+255)/256, 256>>>(w_pos, WPT);
    k_build_p<<<(P4_*PCH_+255)/256, 256>>>(pos2d, P2);
    k_pos<<<(P4_*CIN_+255)/256, 256>>>(WPT, P2, PP);
    k_h0<<<(P16_*136+255)/256, 256>>>(AB, PP, b_pos, SBN, H16+OB_H0);

    // weight preps
    k_wscale<<<(1152+7)/8, 256>>>(w1,    CIN_, 1088, 1088, 1152, 0, RSW1);
    k_wprep<<<(1152*136+255)/256, 256>>>(w1,    CIN_, 1088, 1088, 1152, 0, RSW1, H16+OB_W1);
    k_wscale<<<(1152+7)/8, 256>>>(w2,    CIN_, 1088, 1088, 1152, 0, RSW2);
    k_wprep<<<(1152*136+255)/256, 256>>>(w2,    CIN_, 1088, 1088, 1152, 0, RSW2, H16+OB_W2);
    k_wscale<<<(1152+7)/8, 256>>>(w_ag,  CIN_, 1088, 1088, 1152, 0, RSAG);
    k_wprep<<<(1152*136+255)/256, 256>>>(w_ag,  CIN_, 1088, 1088, 1152, 0, RSAG, H16+OB_WAG);
    k_wscale<<<(1152+7)/8, 256>>>(w_att, CIN_, 1088, 1088, 1152, 0, RSAT);
    k_wprep<<<(1152*136+255)/256, 256>>>(w_att, CIN_, 1088, 1088, 1152, 0, RSAT, H16+OB_WAT);
    k_wscale<<<(640+7)/8, 256>>>(w_ag_s, CIN_, 544, 1088, 640, 0, RSWS);
    k_wprep<<<(640*136+255)/256, 256>>>(w_ag_s, CIN_, 544, 1088, 640, 0, RSWS, H16+OB_WS);
    k_wscale<<<(1152+7)/8, 256>>>(Wsm, 0, 1088, 544, 1152, 2, RS01);
    k_wprep<<<(1152*68+255)/256, 256>>>(Wsm, 0, 1088, 544, 1152, 2, RS01, H16+OB_W01);

    // trunk
    gemm_mma<2><<<dim3(9,128),256,SMEMB>>>(H16+OB_W1, H16+OB_H0,
                                           1088, 34, 1088, nullptr, 0, H16+OB_H1, CIN_,
                                           SBN+2*CIN_, SBN+3*CIN_, RSW1, nullptr, nullptr);
    gemm_mma<3><<<dim3(9,128),256,SMEMB>>>(H16+OB_W2, H16+OB_H1,
                                           1088, 34, 1088, nullptr, 0, H16+OB_H2, CIN_,
                                           SBN+4*CIN_, SBN+5*CIN_, RSW2, H16+OB_H0, nullptr);
    // aggregation branch
    gemm_mma<2><<<dim3(9,128),256,SMEMB>>>(H16+OB_WAG, H16+OB_H2,
                                           1088, 34, 1088, nullptr, 0, H16+OB_G, CIN_,
                                           SBN+6*CIN_, SBN+7*CIN_, RSAG, nullptr, nullptr);
    gemm_mma<4><<<dim3(5,128),256,SMEMB>>>(H16+OB_WS, H16+OB_G,
                                           1088, 34, 544, AG, C_, nullptr, 0,
                                           b_ag_s, nullptr, RSWS, nullptr, nullptr);
    // attention branch: logits fused into GEMM epilogue
    k_attl_init<<<(P16_+255)/256, 256>>>(b_att_s, ATTL);
    gemm_mma<5><<<dim3(9,128),256,SMEMB>>>(H16+OB_WAT, H16+OB_H2,
                                           1088, 34, 1088, ATTL, 0, nullptr, 0,
                                           SBN+8*CIN_, SBN+9*CIN_, RSAT, nullptr, w_att_s);
    k_softmax<<<(P4_+255)/256, 256>>>(ATTL, ATTS);

    // self/transfer stacked: FST = [W0^T; W1^T] @ f
    gemm_mma<0><<<dim3(9,32),256,SMEMB>>>(H16+OB_W01, H16+OB_FB,
                                          544, 17, 1088, FST, CIN_, nullptr, 0,
                                          nullptr, nullptr, RS01, nullptr, nullptr);

    k_fuse<<<(BT_*2176+255)/256, 256>>>(F, FST, AG, ATTS, out);
}

// round 11
// speedup vs baseline: 1.6303x; 1.0682x over previous
#include <cuda_runtime.h>
#include <cuda_fp16.h>
#include <stdint.h>
#include <math.h>

namespace fv {
constexpr int C_ = 544, CIN_ = 1088, BT_ = 1024, P4_ = 4096, P16_ = 16384, PCH_ = 34;
constexpr int KP5 = 576;   // padded K for 544-K GEMMs

// fp32 scratch (elements)
constexpr size_t OF_F    = 0;                              // [P4][544]
constexpr size_t OF_P2   = OF_F    + (size_t)P4_*C_;
constexpr size_t OF_WPT  = OF_P2   + (size_t)P4_*PCH_;
constexpr size_t OF_PP   = OF_WPT  + (size_t)PCH_*CIN_;
constexpr size_t OF_AB   = OF_PP   + (size_t)P4_*CIN_;     // [P4][2176]
constexpr size_t OF_AG   = OF_AB   + (size_t)P4_*2176;     // [P16][544]
constexpr size_t OF_FST  = OF_AG   + (size_t)P16_*C_;      // [P4][1088]
constexpr size_t OF_ATTL = OF_FST  + (size_t)P4_*CIN_;
constexpr size_t OF_ATTS = OF_ATTL + (size_t)P16_;
constexpr size_t OF_SBN  = OF_ATTS + (size_t)P16_;         // [5][2][1088]
constexpr size_t OF_RSWE = OF_SBN  + (size_t)5*2*CIN_;     // 2176
constexpr size_t OF_RSW1 = OF_RSWE + 2176;
constexpr size_t OF_RSW2 = OF_RSW1 + 1152;
constexpr size_t OF_RSAG = OF_RSW2 + 1152;
constexpr size_t OF_RSAT = OF_RSAG + 1152;
constexpr size_t OF_RSWS = OF_RSAT + 1152;                 // 640
constexpr size_t OF_RS01 = OF_RSWS + 640;                  // 1152
constexpr size_t TOT_F32 = OF_RS01 + 1152;

// fp16 row-major scratch [rows][Kpad]
constexpr size_t SZ_FB  = (size_t)P4_ * KP5;
constexpr size_t SZ_H   = (size_t)P16_ * CIN_;
constexpr size_t SZ_WE  = (size_t)2176 * KP5;
constexpr size_t SZ_WB  = (size_t)1152 * 1088;
constexpr size_t SZ_WS  = (size_t)640 * 1088;
constexpr size_t SZ_W01 = (size_t)1152 * KP5;

constexpr size_t OB_FB   = 0;
constexpr size_t OB_H0   = OB_FB   + SZ_FB;
constexpr size_t OB_H1   = OB_H0   + SZ_H;
constexpr size_t OB_H2   = OB_H1   + SZ_H;
constexpr size_t OB_G    = OB_H2   + SZ_H;
constexpr size_t OB_WE   = OB_G    + SZ_H;
constexpr size_t OB_W1   = OB_WE   + SZ_WE;
constexpr size_t OB_W2   = OB_W1   + SZ_WB;
constexpr size_t OB_WAG  = OB_W2   + SZ_WB;
constexpr size_t OB_WAT  = OB_WAG  + SZ_WB;
constexpr size_t OB_WS   = OB_WAT  + SZ_WB;
constexpr size_t OB_W01  = OB_WS   + SZ_WS;
constexpr size_t TOT_H16 = OB_W01  + SZ_W01;
}  // namespace fv

__device__ float  g_F32[fv::TOT_F32];
__device__ __half g_H16[fv::TOT_H16];

using namespace fv;

// ---------------- baseline-PTX helpers ----------------
__device__ __forceinline__ uint32_t smem_u32(const void* p) {
    uint32_t a;
    asm("{ .reg .u64 t; cvta.to.shared.u64 t, %1; cvt.u32.u64 %0, t; }" : "=r"(a) : "l"(p));
    return a;
}
__device__ __forceinline__ void cp16(uint32_t dst, const void* src) {
    asm volatile("cp.async.cg.shared.global [%0], [%1], 16;" :: "r"(dst), "l"(src));
}
#define CP_COMMIT() asm volatile("cp.async.commit_group;" ::: "memory")
#define CP_WAIT(n)  asm volatile("cp.async.wait_group %0;" :: "n"(n) : "memory")

__device__ __forceinline__ void ldsm_x4(uint32_t (&r)[4], uint32_t addr) {
    asm volatile("ldmatrix.sync.aligned.m8n8.x4.shared.b16 {%0,%1,%2,%3}, [%4];"
                 : "=r"(r[0]), "=r"(r[1]), "=r"(r[2]), "=r"(r[3]) : "r"(addr));
}
__device__ __forceinline__ void mma_f16(float (&d)[4], const uint32_t (&a)[4],
                                        const uint32_t (&b)[2]) {
    asm volatile(
        "mma.sync.aligned.m16n8k16.row.col.f32.f16.f16.f32 "
        "{%0,%1,%2,%3}, {%4,%5,%6,%7}, {%8,%9}, {%0,%1,%2,%3};"
        : "+f"(d[0]), "+f"(d[1]), "+f"(d[2]), "+f"(d[3])
        : "r"(a[0]), "r"(a[1]), "r"(a[2]), "r"(a[3]), "r"(b[0]), "r"(b[1]));
}

// ---------------- prep / elementwise ----------------
__global__ void k_bn_fold(const float* __restrict__ b0, const float* __restrict__ b1,
                          const float* __restrict__ b2, const float* __restrict__ b3,
                          const float* __restrict__ b4, float* __restrict__ sbn) {
    int idx = blockIdx.x * blockDim.x + threadIdx.x;
    if (idx >= 5 * CIN_) return;
    int w = idx / CIN_, c = idx % CIN_;
    const float* bn = w == 0 ? b0 : w == 1 ? b1 : w == 2 ? b2 : w == 3 ? b3 : b4;
    float s = bn[c] * rsqrtf(bn[3 * CIN_ + c] + 1e-5f);
    sbn[w * 2 * CIN_ + c] = s;
    sbn[w * 2 * CIN_ + CIN_ + c] = bn[CIN_ + c] - bn[2 * CIN_ + c] * s;
}

__global__ void k_wposT(const float* __restrict__ wpos, float* __restrict__ wpt) {
    int idx = blockIdx.x * blockDim.x + threadIdx.x;
    if (idx >= PCH_ * CIN_) return;
    int k = idx / CIN_, o = idx % CIN_;
    wpt[idx] = wpos[o * PCH_ + k];
}

// weight addressing modes:
// 0: src[r*ld + k]
// 2: stacked Wsm^T: src[(r/544)*295936 + k*544 + (r%544)]
// 3: stacked We:    src[(r%1088)*1088 + (r/1088)*544 + k]
__device__ __forceinline__ float wsrc(const float* src, int ld, int mode, int r, int k) {
    if (mode == 0) return src[(size_t)r * ld + k];
    if (mode == 2) return src[(size_t)(r / 544) * 295936 + (size_t)k * 544 + (r % 544)];
    return src[(size_t)(r % 1088) * 1088 + (size_t)(r / 1088) * 544 + k];
}

__global__ void k_wscale(const float* __restrict__ src, int ld, int Msrc, int K,
                         int MP, int mode, float* __restrict__ rs) {
    int w = threadIdx.x >> 5, lane = threadIdx.x & 31;
    int r = blockIdx.x * 8 + w;
    if (r >= MP) return;
    float mx = 0.f;
    if (r < Msrc)
        for (int k = lane; k < K; k += 32) mx = fmaxf(mx, fabsf(wsrc(src, ld, mode, r, k)));
#pragma unroll
    for (int o = 16; o > 0; o >>= 1) mx = fmaxf(mx, __shfl_xor_sync(0xFFFFFFFFu, mx, o));
    if (lane == 0) {
        int e = 0;
        if (mx > 0.f) frexpf(mx, &e);
        rs[r] = exp2f((float)e);
    }
}

// weight -> row-major [MP][Kp] fp16 (row-scaled); zero-padded beyond Msrc/Ksrc
__global__ void k_wprep(const float* __restrict__ src, int ld, int Msrc, int Ksrc, int Kp,
                        int MP, int mode, const float* __restrict__ rs,
                        __half* __restrict__ hi) {
    int K8 = Kp >> 3;
    int idx = blockIdx.x * blockDim.x + threadIdx.x;
    if (idx >= MP * K8) return;
    int r = idx / K8, k0 = (idx % K8) * 8;
    float inv = 1.0f / rs[r];
    union { __half h[8]; uint4 v; } ph;
#pragma unroll
    for (int e = 0; e < 8; e++) {
        int k = k0 + e;
        float x = (r < Msrc && k < Ksrc) ? wsrc(src, ld, mode, r, k) * inv : 0.f;
        ph.h[e] = __float2half(x);
    }
    *reinterpret_cast<uint4*>(hi + (size_t)r * Kp + k0) = ph.v;
}

__global__ void k_build_f(const float* __restrict__ x, float* __restrict__ F,
                          __half* __restrict__ fb) {
    int idx = blockIdx.x * blockDim.x + threadIdx.x;
    if (idx >= P4_ * 72) return;
    int p = idx / 72, c0 = (idx % 72) * 8;
    int bt = p >> 2, n = p & 3;
    union { __half h[8]; uint4 v; } ph;
    float vv[8];
#pragma unroll
    for (int e = 0; e < 8; e++) {
        int c = c0 + e;
        vv[e] = (c < C_) ? x[((size_t)bt * C_ + c) * 4 + n] : 0.f;
        ph.h[e] = __float2half(vv[e]);
    }
    *reinterpret_cast<uint4*>(fb + (size_t)p * KP5 + c0) = ph.v;
    if (c0 < C_) {
        float4* d = reinterpret_cast<float4*>(F + (size_t)p * C_ + c0);
        d[0] = make_float4(vv[0], vv[1], vv[2], vv[3]);
        d[1] = make_float4(vv[4], vv[5], vv[6], vv[7]);
    }
}

__global__ void k_build_p(const float* __restrict__ pos, float* __restrict__ P2) {
    int idx = blockIdx.x * blockDim.x + threadIdx.x;
    if (idx >= P4_ * PCH_) return;
    int p = idx / PCH_, k = idx % PCH_;
    P2[idx] = pos[((size_t)(p >> 2) * PCH_ + k) * 4 + (p & 3)];
}

__global__ void k_pos(const float* __restrict__ wpt, const float* __restrict__ P2,
                      float* __restrict__ PP) {
    int idx = blockIdx.x * blockDim.x + threadIdx.x;
    if (idx >= P4_ * CIN_) return;
    int p = idx / CIN_, o = idx % CIN_;
    float acc = 0.f;
#pragma unroll
    for (int k = 0; k < PCH_; k++) acc = fmaf(wpt[k * CIN_ + o], P2[p * PCH_ + k], acc);
    PP[idx] = acc;
}

__global__ void k_h0(const float* __restrict__ AB, const float* __restrict__ PP,
                     const float* __restrict__ bpos, const float* __restrict__ sbn,
                     __half* __restrict__ hh) {
    int idx = blockIdx.x * blockDim.x + threadIdx.x;
    if (idx >= P16_ * 136) return;
    int p16 = idx / 136, o0 = (idx % 136) * 8;
    int bt = p16 >> 4, ij = p16 & 15, i = ij >> 2, j = ij & 3;
    size_t pa = (size_t)(bt * 4 + i) * 2176 + o0;
    size_t pb = (size_t)(bt * 4 + j) * 2176 + 1088 + o0;
    size_t qi = (size_t)(bt * 4 + i) * CIN_ + o0;
    size_t qj = (size_t)(bt * 4 + j) * CIN_ + o0;
    union { __half h[8]; uint4 v; } ph;
#pragma unroll
    for (int e = 0; e < 8; e++) {
        int o = o0 + e;
        float v = fmaxf(fmaf(sbn[o], AB[pa + e] + AB[pb + e], sbn[CIN_ + o]), 0.f);
        v += PP[qi + e] - PP[qj + e] + bpos[o];
        ph.h[e] = __float2half(v);
    }
    *reinterpret_cast<uint4*>(hh + (size_t)p16 * CIN_ + o0) = ph.v;
}

__global__ void k_attl_init(const float* __restrict__ b, float* __restrict__ L) {
    int p = blockIdx.x * blockDim.x + threadIdx.x;
    if (p < P16_) L[p] = b[0];
}

__global__ void k_softmax(const float* __restrict__ L, float* __restrict__ S) {
    int r = blockIdx.x * blockDim.x + threadIdx.x;
    if (r >= P4_) return;
    float l0 = L[r*4], l1 = L[r*4+1], l2 = L[r*4+2], l3 = L[r*4+3];
    float m = fmaxf(fmaxf(l0, l1), fmaxf(l2, l3));
    float e0 = __expf(l0-m), e1 = __expf(l1-m), e2 = __expf(l2-m), e3 = __expf(l3-m);
    float inv = 1.f / (e0+e1+e2+e3);
    S[r*4]=e0*inv; S[r*4+1]=e1*inv; S[r*4+2]=e2*inv; S[r*4+3]=e3*inv;
}

__global__ void k_fuse(const float* __restrict__ F, const float* __restrict__ FST,
                       const float* __restrict__ AG, const float* __restrict__ S,
                       float* __restrict__ out) {
    int idx = blockIdx.x * blockDim.x + threadIdx.x;
    if (idx >= BT_ * 2176) return;
    int bt = idx / 2176, rem = idx % 2176;
    int i = rem / C_, d = rem % C_;
    int ri = bt * 4 + i;
    float acc = F[(size_t)ri * C_ + d];
#pragma unroll
    for (int j = 0; j < 4; j++) {
        float a = S[ri * 4 + j];
        if (j == i) acc = fmaf(FST[(size_t)ri * CIN_ + d], a, acc);
        else acc = fmaf(FST[(size_t)(bt*4+j) * CIN_ + 544 + d] *
                        AG[(size_t)(bt*16+i*4+j) * C_ + d], a, acc);
    }
    out[(size_t)bt * 2176 + d * 4 + i] = acc;
}

// ---------------- HMMA fp16 GEMM: 128x128 tile, BK=64 stages, 3-stage pipe ----------------
// C[m][n] = A[MP][Kp] @ B[NP][Kp]^T, per-row scale rs applied in epilogue.
// EPI: 0 v*rs fp32 | 2 relu->fp16 | 3 fp16resid+relu->fp16 | 4 v*rs+bias fp32 | 5 att-dot atomic
constexpr int TIL = 16384;       // 128 rows x 128 B
constexpr int STG = 2 * TIL;     // A|B = 32 KB
constexpr int SMEMB = 98304;     // 3 stages (Cs 128x132 f32 = 67.6 KB aliases)

__device__ __forceinline__ uint32_t swadr(uint32_t base, int row, int c16) {
    return base + row * 128 + ((c16 ^ (row & 7)) << 4);
}

template <int EPI>
__global__ void __launch_bounds__(256, 2)
gemm_mma(const __half* __restrict__ Ag, const __half* __restrict__ Bg,
         int K, int KB, int Mreal,
         float* __restrict__ outf, int ldo,
         __half* __restrict__ oh, int ldob,
         const float* __restrict__ sv, const float* __restrict__ tv,
         const float* __restrict__ rs,
         const __half* __restrict__ r16,
         const float* __restrict__ watt) {
    extern __shared__ __half smbuf[];
    const uint32_t sb = smem_u32(smbuf);
    const int tid = threadIdx.x, lane = tid & 31, wid = tid >> 5;
    const int mt = blockIdx.x, nt = blockIdx.y;
    // 4x2 warp grid: warp tile 32 (M) x 64 (N)
    const int wm = (wid & 3) * 32, wn = (wid >> 2) * 64;

    float acc[2][8][4];
#pragma unroll
    for (int a = 0; a < 2; a++)
#pragma unroll
        for (int b = 0; b < 8; b++)
#pragma unroll
            for (int c = 0; c < 4; c++) acc[a][b][c] = 0.f;

    auto load_stage = [&](int s, int kb) {
        uint32_t dstb = sb + s * STG;
        int k0 = kb * 64;
#pragma unroll
        for (int c = 0; c < 4; c++) {
            int q = tid + c * 256;
            int r = q >> 3, ch = q & 7;
            uint32_t d = dstb + r * 128 + ((ch ^ (r & 7)) << 4);
            size_t offA = (size_t)(mt * 128 + r) * K + k0 + ch * 8;
            size_t offB = (size_t)(nt * 128 + r) * K + k0 + ch * 8;
            cp16(d,       Ag + offA);
            cp16(d + TIL, Bg + offB);
        }
    };

    const int grp = lane >> 3, lrow = lane & 7;

    auto compute_stage = [&](int s) {
        uint32_t base = sb + s * STG;
#pragma unroll
        for (int ks2 = 0; ks2 < 4; ks2++) {
            uint32_t ah[2][4], bf[8][2];
            const int cA = ks2 * 2 + (grp >> 1);
            const int cB = ks2 * 2 + (grp & 1);
#pragma unroll
            for (int mi = 0; mi < 2; mi++) {
                int row = wm + mi * 16 + (grp & 1) * 8 + lrow;
                ldsm_x4(ah[mi], swadr(base, row, cA));
            }
#pragma unroll
            for (int n2 = 0; n2 < 4; n2++) {
                int row = wn + n2 * 16 + (grp >> 1) * 8 + lrow;
                uint32_t q[4];
                ldsm_x4(q, swadr(base + TIL, row, cB));
                bf[n2 * 2][0] = q[0]; bf[n2 * 2][1] = q[1];
                bf[n2 * 2 + 1][0] = q[2]; bf[n2 * 2 + 1][1] = q[3];
            }
#pragma unroll
            for (int mi = 0; mi < 2; mi++)
#pragma unroll
                for (int ni = 0; ni < 8; ni++) mma_f16(acc[mi][ni], ah[mi], bf[ni]);
        }
    };

    load_stage(0, 0); CP_COMMIT();
    if (KB > 1) { load_stage(1, 1); CP_COMMIT(); }
    for (int kb = 0; kb < KB; kb++) {
        if (kb + 1 < KB) { CP_WAIT(1); } else { CP_WAIT(0); }
        __syncthreads();
        if (kb + 2 < KB) { load_stage((kb + 2) % 3, kb + 2); CP_COMMIT(); }
        compute_stage(kb % 3);
    }
    __syncthreads();

    // transpose through smem: Cs[n (128)][m (128 + pad 4)]
    float* Cs = reinterpret_cast<float*>(smbuf);
#pragma unroll
    for (int mi = 0; mi < 2; mi++)
#pragma unroll
        for (int ni = 0; ni < 8; ni++) {
            int rm = wm + mi * 16 + (lane >> 2);
            int cn = wn + ni * 8 + 2 * (lane & 3);
            Cs[cn * 132 + rm]           = acc[mi][ni][0];
            Cs[(cn + 1) * 132 + rm]     = acc[mi][ni][1];
            Cs[cn * 132 + rm + 8]       = acc[mi][ni][2];
            Cs[(cn + 1) * 132 + rm + 8] = acc[mi][ni][3];
        }
    __syncthreads();

    {
        int nl = tid >> 1, m0 = (tid & 1) * 64;
        int ng = nt * 128 + nl;
        int mg0 = mt * 128 + m0;
        if constexpr (EPI == 5) {
            float wsum = 0.f;
#pragma unroll 8
            for (int j = 0; j < 64; j++) {
                int m = mg0 + j;
                if (m >= Mreal) break;
                float v = Cs[nl * 132 + m0 + j] * rs[m];
                wsum = fmaf(fmaxf(fmaf(sv[m], v, tv[m]), 0.f), watt[m], wsum);
            }
            atomicAdd(&outf[ng], wsum);
        } else if constexpr (EPI == 2 || EPI == 3) {
#pragma unroll
            for (int j0 = 0; j0 < 64; j0 += 8) {
                if (mg0 + j0 >= Mreal) break;
                union { __half h[8]; uint4 v; } ph;
                float rv[8];
                if constexpr (EPI == 3) {
                    uint4 r4 = *reinterpret_cast<const uint4*>(r16 + (size_t)ng * ldob + mg0 + j0);
                    const __half* rr = reinterpret_cast<const __half*>(&r4);
#pragma unroll
                    for (int e = 0; e < 8; e++) rv[e] = __half2float(rr[e]);
                }
#pragma unroll
                for (int e = 0; e < 8; e++) {
                    int m = mg0 + j0 + e;
                    float v = Cs[nl * 132 + m0 + j0 + e] * rs[m];
                    float w = fmaxf(fmaf(sv[m], v, tv[m]), 0.f);
                    if constexpr (EPI == 3) w += rv[e];
                    ph.h[e] = __float2half(w);
                }
                *reinterpret_cast<uint4*>(oh + (size_t)ng * ldob + mg0 + j0) = ph.v;
            }
        } else {
#pragma unroll
            for (int j0 = 0; j0 < 64; j0 += 4) {
                if (mg0 + j0 >= Mreal) break;
                float4 ov;
                float* pv = reinterpret_cast<float*>(&ov);
#pragma unroll
                for (int e = 0; e < 4; e++) {
                    int m = mg0 + j0 + e;
                    float v = Cs[nl * 132 + m0 + j0 + e] * rs[m];
                    if constexpr (EPI == 4) v = v + sv[m];
                    pv[e] = v;
                }
                *reinterpret_cast<float4*>(outf + (size_t)ng * ldo + mg0 + j0) = ov;
            }
        }
    }
}

// ---------------- launch ----------------
extern "C" void kernel_launch(void* const* d_in, const int* in_sizes, int n_in,
                              void* d_out, int out_size) {
    const float *x = (const float*)d_in[0], *pos2d = (const float*)d_in[1];
    const float *w_pos = (const float*)d_in[2], *b_pos = (const float*)d_in[3];
    const float *w_e = (const float*)d_in[4],  *w1 = (const float*)d_in[6];
    const float *w2 = (const float*)d_in[8],   *w_ag = (const float*)d_in[10];
    const float *w_ag_s = (const float*)d_in[12], *b_ag_s = (const float*)d_in[13];
    const float *w_att = (const float*)d_in[14], *w_att_s = (const float*)d_in[16];
    const float *b_att_s = (const float*)d_in[17], *Wsm = (const float*)d_in[18];
    float* out = (float*)d_out;

    float* F32 = nullptr;  __half* H16 = nullptr;
    cudaGetSymbolAddress((void**)&F32, g_F32);
    cudaGetSymbolAddress((void**)&H16, g_H16);

    float *F = F32+OF_F, *P2 = F32+OF_P2, *WPT = F32+OF_WPT, *PP = F32+OF_PP;
    float *AB = F32+OF_AB, *AG = F32+OF_AG, *FST = F32+OF_FST;
    float *ATTL = F32+OF_ATTL, *ATTS = F32+OF_ATTS, *SBN = F32+OF_SBN;
    float *RSWE = F32+OF_RSWE, *RSW1 = F32+OF_RSW1, *RSW2 = F32+OF_RSW2;
    float *RSAG = F32+OF_RSAG, *RSAT = F32+OF_RSAT, *RSWS = F32+OF_RSWS, *RS01 = F32+OF_RS01;

    cudaFuncSetAttribute(gemm_mma<0>, cudaFuncAttributeMaxDynamicSharedMemorySize, SMEMB);
    cudaFuncSetAttribute(gemm_mma<2>, cudaFuncAttributeMaxDynamicSharedMemorySize, SMEMB);
    cudaFuncSetAttribute(gemm_mma<3>, cudaFuncAttributeMaxDynamicSharedMemorySize, SMEMB);
    cudaFuncSetAttribute(gemm_mma<4>, cudaFuncAttributeMaxDynamicSharedMemorySize, SMEMB);
    cudaFuncSetAttribute(gemm_mma<5>, cudaFuncAttributeMaxDynamicSharedMemorySize, SMEMB);

    // launches 1-3, then the big layer-1 GEMM at slot 4 (ncu captures the 4th launch)
    k_build_f<<<(P4_*72+255)/256, 256>>>(x, F, H16+OB_FB);
    k_wscale<<<(2176+7)/8, 256>>>(w_e, 0, 2176, 544, 2176, 3, RSWE);
    k_wprep<<<(2176*72+255)/256, 256>>>(w_e, 0, 2176, 544, KP5, 2176, 3, RSWE, H16+OB_WE);
    gemm_mma<0><<<dim3(17,32),256,SMEMB>>>(H16+OB_WE, H16+OB_FB,
                                           KP5, 9, 2176, AB, 2176, nullptr, 0,
                                           nullptr, nullptr, RSWE, nullptr, nullptr);

    k_bn_fold<<<(5*CIN_+255)/256, 256>>>((const float*)d_in[5], (const float*)d_in[7],
                                         (const float*)d_in[9], (const float*)d_in[11],
                                         (const float*)d_in[15], SBN);
    k_wposT<<<(PCH_*CIN_+255)/256, 256>>>(w_pos, WPT);
    k_build_p<<<(P4_*PCH_+255)/256, 256>>>(pos2d, P2);
    k_pos<<<(P4_*CIN_+255)/256, 256>>>(WPT, P2, PP);
    k_h0<<<(P16_*136+255)/256, 256>>>(AB, PP, b_pos, SBN, H16+OB_H0);

    // weight preps
    k_wscale<<<(1152+7)/8, 256>>>(w1,    CIN_, 1088, 1088, 1152, 0, RSW1);
    k_wprep<<<(1152*136+255)/256, 256>>>(w1,    CIN_, 1088, 1088, 1088, 1152, 0, RSW1, H16+OB_W1);
    k_wscale<<<(1152+7)/8, 256>>>(w2,    CIN_, 1088, 1088, 1152, 0, RSW2);
    k_wprep<<<(1152*136+255)/256, 256>>>(w2,    CIN_, 1088, 1088, 1088, 1152, 0, RSW2, H16+OB_W2);
    k_wscale<<<(1152+7)/8, 256>>>(w_ag,  CIN_, 1088, 1088, 1152, 0, RSAG);
    k_wprep<<<(1152*136+255)/256, 256>>>(w_ag,  CIN_, 1088, 1088, 1088, 1152, 0, RSAG, H16+OB_WAG);
    k_wscale<<<(1152+7)/8, 256>>>(w_att, CIN_, 1088, 1088, 1152, 0, RSAT);
    k_wprep<<<(1152*136+255)/256, 256>>>(w_att, CIN_, 1088, 1088, 1088, 1152, 0, RSAT, H16+OB_WAT);
    k_wscale<<<(640+7)/8, 256>>>(w_ag_s, CIN_, 544, 1088, 640, 0, RSWS);
    k_wprep<<<(640*136+255)/256, 256>>>(w_ag_s, CIN_, 544, 1088, 1088, 640, 0, RSWS, H16+OB_WS);
    k_wscale<<<(1152+7)/8, 256>>>(Wsm, 0, 1088, 544, 1152, 2, RS01);
    k_wprep<<<(1152*72+255)/256, 256>>>(Wsm, 0, 1088, 544, KP5, 1152, 2, RS01, H16+OB_W01);

    // trunk
    gemm_mma<2><<<dim3(9,128),256,SMEMB>>>(H16+OB_W1, H16+OB_H0,
                                           1088, 17, 1088, nullptr, 0, H16+OB_H1, CIN_,
                                           SBN+2*CIN_, SBN+3*CIN_, RSW1, nullptr, nullptr);
    gemm_mma<3><<<dim3(9,128),256,SMEMB>>>(H16+OB_W2, H16+OB_H1,
                                           1088, 17, 1088, nullptr, 0, H16+OB_H2, CIN_,
                                           SBN+4*CIN_, SBN+5*CIN_, RSW2, H16+OB_H0, nullptr);
    // aggregation branch
    gemm_mma<2><<<dim3(9,128),256,SMEMB>>>(H16+OB_WAG, H16+OB_H2,
                                           1088, 17, 1088, nullptr, 0, H16+OB_G, CIN_,
                                           SBN+6*CIN_, SBN+7*CIN_, RSAG, nullptr, nullptr);
    gemm_mma<4><<<dim3(5,128),256,SMEMB>>>(H16+OB_WS, H16+OB_G,
                                           1088, 17, 544, AG, C_, nullptr, 0,
                                           b_ag_s, nullptr, RSWS, nullptr, nullptr);
    // attention branch: logits fused into GEMM epilogue
    k_attl_init<<<(P16_+255)/256, 256>>>(b_att_s, ATTL);
    gemm_mma<5><<<dim3(9,128),256,SMEMB>>>(H16+OB_WAT, H16+OB_H2,
                                           1088, 17, 1088, ATTL, 0, nullptr, 0,
                                           SBN+8*CIN_, SBN+9*CIN_, RSAT, nullptr, w_att_s);
    k_softmax<<<(P4_+255)/256, 256>>>(ATTL, ATTS);

    // self/transfer stacked: FST = [W0^T; W1^T] @ f
    gemm_mma<0><<<dim3(9,32),256,SMEMB>>>(H16+OB_W01, H16+OB_FB,
                                          KP5, 9, 1088, FST, CIN_, nullptr, 0,
                                          nullptr, nullptr, RS01, nullptr, nullptr);

    k_fuse<<<(BT_*2176+255)/256, 256>>>(F, FST, AG, ATTS, out);
}

// round 12
// speedup vs baseline: 1.6971x; 1.0409x over previous
#include <cuda_runtime.h>
#include <cuda_fp16.h>
#include <stdint.h>
#include <math.h>

namespace fv {
constexpr int C_ = 544, CIN_ = 1088, BT_ = 1024, P4_ = 4096, P16_ = 16384, PCH_ = 34;
constexpr int KP5 = 576;   // padded K for 544-K GEMMs

// fp32 scratch (elements)
constexpr size_t OF_F    = 0;                              // [P4][544]
constexpr size_t OF_P2   = OF_F    + (size_t)P4_*C_;
constexpr size_t OF_WPT  = OF_P2   + (size_t)P4_*PCH_;
constexpr size_t OF_PP   = OF_WPT  + (size_t)PCH_*CIN_;
constexpr size_t OF_AB   = OF_PP   + (size_t)P4_*CIN_;     // [P4][2176]
constexpr size_t OF_AG   = OF_AB   + (size_t)P4_*2176;     // [P16][544]
constexpr size_t OF_FST  = OF_AG   + (size_t)P16_*C_;      // [P4][1088]
constexpr size_t OF_ATTL = OF_FST  + (size_t)P4_*CIN_;
constexpr size_t OF_ATTS = OF_ATTL + (size_t)P16_;
constexpr size_t OF_SBN  = OF_ATTS + (size_t)P16_;         // [5][2][1088]
constexpr size_t OF_RSWE = OF_SBN  + (size_t)5*2*CIN_;     // 2176
constexpr size_t OF_RSW1 = OF_RSWE + 2176;                 // 1152
constexpr size_t OF_RSW2 = OF_RSW1 + 1152;
constexpr size_t OF_RSGA = OF_RSW2 + 1152;                 // 2176 (stacked ag|att)
constexpr size_t OF_RSWS = OF_RSGA + 2176;                 // 640
constexpr size_t OF_RS01 = OF_RSWS + 640;                  // 1152
constexpr size_t OF_S6   = OF_RS01 + 1152;                 // 2176
constexpr size_t OF_T6   = OF_S6   + 2176;
constexpr size_t OF_WT2  = OF_T6   + 2176;
constexpr size_t TOT_F32 = OF_WT2 + 2176;

// fp16 row-major scratch [rows][Kpad]
constexpr size_t SZ_FB   = (size_t)P4_ * KP5;
constexpr size_t SZ_H    = (size_t)P16_ * CIN_;
constexpr size_t SZ_WE   = (size_t)2176 * KP5;
constexpr size_t SZ_WB   = (size_t)1152 * 1088;
constexpr size_t SZ_WGA  = (size_t)2176 * 1088;
constexpr size_t SZ_WS   = (size_t)640 * 1088;
constexpr size_t SZ_W01  = (size_t)1152 * KP5;

constexpr size_t OB_FB   = 0;
constexpr size_t OB_H0   = OB_FB   + SZ_FB;
constexpr size_t OB_H1   = OB_H0   + SZ_H;
constexpr size_t OB_H2   = OB_H1   + SZ_H;
constexpr size_t OB_G    = OB_H2   + SZ_H;
constexpr size_t OB_WE   = OB_G    + SZ_H;
constexpr size_t OB_W1   = OB_WE   + SZ_WE;
constexpr size_t OB_W2   = OB_W1   + SZ_WB;
constexpr size_t OB_WGA  = OB_W2   + SZ_WB;
constexpr size_t OB_WS   = OB_WGA  + SZ_WGA;
constexpr size_t OB_W01  = OB_WS   + SZ_WS;
constexpr size_t TOT_H16 = OB_W01  + SZ_W01;
}  // namespace fv

__device__ float  g_F32[fv::TOT_F32];
__device__ __half g_H16[fv::TOT_H16];

using namespace fv;

// ---------------- baseline-PTX helpers ----------------
__device__ __forceinline__ uint32_t smem_u32(const void* p) {
    uint32_t a;
    asm("{ .reg .u64 t; cvta.to.shared.u64 t, %1; cvt.u32.u64 %0, t; }" : "=r"(a) : "l"(p));
    return a;
}
__device__ __forceinline__ void cp16(uint32_t dst, const void* src) {
    asm volatile("cp.async.cg.shared.global [%0], [%1], 16;" :: "r"(dst), "l"(src));
}
#define CP_COMMIT() asm volatile("cp.async.commit_group;" ::: "memory")
#define CP_WAIT(n)  asm volatile("cp.async.wait_group %0;" :: "n"(n) : "memory")

__device__ __forceinline__ void ldsm_x4(uint32_t (&r)[4], uint32_t addr) {
    asm volatile("ldmatrix.sync.aligned.m8n8.x4.shared.b16 {%0,%1,%2,%3}, [%4];"
                 : "=r"(r[0]), "=r"(r[1]), "=r"(r[2]), "=r"(r[3]) : "r"(addr));
}
__device__ __forceinline__ void mma_f16(float (&d)[4], const uint32_t (&a)[4],
                                        const uint32_t (&b)[2]) {
    asm volatile(
        "mma.sync.aligned.m16n8k16.row.col.f32.f16.f16.f32 "
        "{%0,%1,%2,%3}, {%4,%5,%6,%7}, {%8,%9}, {%0,%1,%2,%3};"
        : "+f"(d[0]), "+f"(d[1]), "+f"(d[2]), "+f"(d[3])
        : "r"(a[0]), "r"(a[1]), "r"(a[2]), "r"(a[3]), "r"(b[0]), "r"(b[1]));
}

// ---------------- prep / elementwise ----------------
__global__ void k_bn_fold(const float* __restrict__ b0, const float* __restrict__ b1,
                          const float* __restrict__ b2, const float* __restrict__ b3,
                          const float* __restrict__ b4, float* __restrict__ sbn) {
    int idx = blockIdx.x * blockDim.x + threadIdx.x;
    if (idx >= 5 * CIN_) return;
    int w = idx / CIN_, c = idx % CIN_;
    const float* bn = w == 0 ? b0 : w == 1 ? b1 : w == 2 ? b2 : w == 3 ? b3 : b4;
    float s = bn[c] * rsqrtf(bn[3 * CIN_ + c] + 1e-5f);
    sbn[w * 2 * CIN_ + c] = s;
    sbn[w * 2 * CIN_ + CIN_ + c] = bn[CIN_ + c] - bn[2 * CIN_ + c] * s;
}

__global__ void k_wposT(const float* __restrict__ wpos, float* __restrict__ wpt) {
    int idx = blockIdx.x * blockDim.x + threadIdx.x;
    if (idx >= PCH_ * CIN_) return;
    int k = idx / CIN_, o = idx % CIN_;
    wpt[idx] = wpos[o * PCH_ + k];
}

// weight fetch modes:
// 0: srcA[r*ld + k]
// 2: stacked Wsm^T: srcA[(r/544)*295936 + k*544 + (r%544)]
// 3: stacked We:    srcA[(r%1088)*1088 + (r/1088)*544 + k]
// 5: two stacked:   r<1088 ? srcA[r*1088+k] : srcB[(r-1088)*1088+k]
__device__ __forceinline__ float wfetch(const float* srcA, const float* srcB,
                                        int ld, int mode, int r, int k) {
    if (mode == 0) return srcA[(size_t)r * ld + k];
    if (mode == 2) return srcA[(size_t)(r / 544) * 295936 + (size_t)k * 544 + (r % 544)];
    if (mode == 3) return srcA[(size_t)(r % 1088) * 1088 + (size_t)(r / 1088) * 544 + k];
    return (r < 1088) ? srcA[(size_t)r * 1088 + k] : srcB[(size_t)(r - 1088) * 1088 + k];
}

// fused per-row scale + fp16 convert; one warp per row
__global__ void k_wsp(const float* __restrict__ srcA, const float* __restrict__ srcB,
                      int ld, int Msrc, int Ksrc, int Kp, int MP, int mode,
                      float* __restrict__ rs, __half* __restrict__ dst) {
    int wid = threadIdx.x >> 5, lane = threadIdx.x & 31;
    int r = blockIdx.x * 8 + wid;
    if (r >= MP) return;
    float mx = 0.f;
    if (r < Msrc)
        for (int k = lane; k < Ksrc; k += 32)
            mx = fmaxf(mx, fabsf(wfetch(srcA, srcB, ld, mode, r, k)));
#pragma unroll
    for (int o = 16; o > 0; o >>= 1) mx = fmaxf(mx, __shfl_xor_sync(0xFFFFFFFFu, mx, o));
    int e = 0;
    if (mx > 0.f) frexpf(mx, &e);
    float rsv = exp2f((float)e);
    if (lane == 0) rs[r] = rsv;
    float inv = 1.0f / rsv;
    for (int k0 = lane * 8; k0 < Kp; k0 += 256) {
        union { __half h[8]; uint4 v; } ph;
#pragma unroll
        for (int ee = 0; ee < 8; ee++) {
            int k = k0 + ee;
            float x = (r < Msrc && k < Ksrc) ? wfetch(srcA, srcB, ld, mode, r, k) * inv : 0.f;
            ph.h[ee] = __float2half(x);
        }
        *reinterpret_cast<uint4*>(dst + (size_t)r * Kp + k0) = ph.v;
    }
}

// stacked ag|att epilogue constants: s/t/watt indexed by stacked row
__global__ void k_combine(const float* __restrict__ sbn, const float* __restrict__ watt_s,
                          float* __restrict__ s6, float* __restrict__ t6,
                          float* __restrict__ wt2) {
    int m = blockIdx.x * blockDim.x + threadIdx.x;
    if (m >= 2176) return;
    if (m < 1088) {
        s6[m] = sbn[6 * CIN_ + m];
        t6[m] = sbn[7 * CIN_ + m];
        wt2[m] = 0.f;
    } else {
        int c = m - 1088;
        s6[m] = sbn[8 * CIN_ + c];
        t6[m] = sbn[9 * CIN_ + c];
        wt2[m] = watt_s[c];
    }
}

__global__ void k_build_f(const float* __restrict__ x, float* __restrict__ F,
                          __half* __restrict__ fb) {
    int idx = blockIdx.x * blockDim.x + threadIdx.x;
    if (idx >= P4_ * 72) return;
    int p = idx / 72, c0 = (idx % 72) * 8;
    int bt = p >> 2, n = p & 3;
    union { __half h[8]; uint4 v; } ph;
    float vv[8];
#pragma unroll
    for (int e = 0; e < 8; e++) {
        int c = c0 + e;
        vv[e] = (c < C_) ? x[((size_t)bt * C_ + c) * 4 + n] : 0.f;
        ph.h[e] = __float2half(vv[e]);
    }
    *reinterpret_cast<uint4*>(fb + (size_t)p * KP5 + c0) = ph.v;
    if (c0 < C_) {
        float4* d = reinterpret_cast<float4*>(F + (size_t)p * C_ + c0);
        d[0] = make_float4(vv[0], vv[1], vv[2], vv[3]);
        d[1] = make_float4(vv[4], vv[5], vv[6], vv[7]);
    }
}

__global__ void k_build_p(const float* __restrict__ pos, float* __restrict__ P2) {
    int idx = blockIdx.x * blockDim.x + threadIdx.x;
    if (idx >= P4_ * PCH_) return;
    int p = idx / PCH_, k = idx % PCH_;
    P2[idx] = pos[((size_t)(p >> 2) * PCH_ + k) * 4 + (p & 3)];
}

__global__ void k_pos(const float* __restrict__ wpt, const float* __restrict__ P2,
                      float* __restrict__ PP) {
    int idx = blockIdx.x * blockDim.x + threadIdx.x;
    if (idx >= P4_ * CIN_) return;
    int p = idx / CIN_, o = idx % CIN_;
    float acc = 0.f;
#pragma unroll
    for (int k = 0; k < PCH_; k++) acc = fmaf(wpt[k * CIN_ + o], P2[p * PCH_ + k], acc);
    PP[idx] = acc;
}

__global__ void k_h0(const float* __restrict__ AB, const float* __restrict__ PP,
                     const float* __restrict__ bpos, const float* __restrict__ sbn,
                     __half* __restrict__ hh) {
    int idx = blockIdx.x * blockDim.x + threadIdx.x;
    if (idx >= P16_ * 136) return;
    int p16 = idx / 136, o0 = (idx % 136) * 8;
    int bt = p16 >> 4, ij = p16 & 15, i = ij >> 2, j = ij & 3;
    size_t pa = (size_t)(bt * 4 + i) * 2176 + o0;
    size_t pb = (size_t)(bt * 4 + j) * 2176 + 1088 + o0;
    size_t qi = (size_t)(bt * 4 + i) * CIN_ + o0;
    size_t qj = (size_t)(bt * 4 + j) * CIN_ + o0;
    union { __half h[8]; uint4 v; } ph;
#pragma unroll
    for (int e = 0; e < 8; e++) {
        int o = o0 + e;
        float v = fmaxf(fmaf(sbn[o], AB[pa + e] + AB[pb + e], sbn[CIN_ + o]), 0.f);
        v += PP[qi + e] - PP[qj + e] + bpos[o];
        ph.h[e] = __float2half(v);
    }
    *reinterpret_cast<uint4*>(hh + (size_t)p16 * CIN_ + o0) = ph.v;
}

__global__ void k_attl_init(const float* __restrict__ b, float* __restrict__ L) {
    int p = blockIdx.x * blockDim.x + threadIdx.x;
    if (p < P16_) L[p] = b[0];
}

__global__ void k_softmax(const float* __restrict__ L, float* __restrict__ S) {
    int r = blockIdx.x * blockDim.x + threadIdx.x;
    if (r >= P4_) return;
    float l0 = L[r*4], l1 = L[r*4+1], l2 = L[r*4+2], l3 = L[r*4+3];
    float m = fmaxf(fmaxf(l0, l1), fmaxf(l2, l3));
    float e0 = __expf(l0-m), e1 = __expf(l1-m), e2 = __expf(l2-m), e3 = __expf(l3-m);
    float inv = 1.f / (e0+e1+e2+e3);
    S[r*4]=e0*inv; S[r*4+1]=e1*inv; S[r*4+2]=e2*inv; S[r*4+3]=e3*inv;
}

__global__ void k_fuse(const float* __restrict__ F, const float* __restrict__ FST,
                       const float* __restrict__ AG, const float* __restrict__ S,
                       float* __restrict__ out) {
    int idx = blockIdx.x * blockDim.x + threadIdx.x;
    if (idx >= BT_ * 2176) return;
    int bt = idx / 2176, rem = idx % 2176;
    int i = rem / C_, d = rem % C_;
    int ri = bt * 4 + i;
    float acc = F[(size_t)ri * C_ + d];
#pragma unroll
    for (int j = 0; j < 4; j++) {
        float a = S[ri * 4 + j];
        if (j == i) acc = fmaf(FST[(size_t)ri * CIN_ + d], a, acc);
        else acc = fmaf(FST[(size_t)(bt*4+j) * CIN_ + 544 + d] *
                        AG[(size_t)(bt*16+i*4+j) * C_ + d], a, acc);
    }
    out[(size_t)bt * 2176 + d * 4 + i] = acc;
}

// ---------------- HMMA fp16 GEMM: 128x128 tile, BK=64, 3-stage pipe ----------------
// EPI: 0 v*rs fp32 | 2 relu->fp16 | 3 fp16resid+relu->fp16 | 4 v*rs+bias fp32
//      | 6 hybrid stacked: m<1088 relu->fp16 G, m>=1088 att-dot atomicAdd
constexpr int TIL = 16384;       // 128 rows x 128 B
constexpr int STG = 2 * TIL;     // A|B = 32 KB
constexpr int SMEMB = 98304;     // 3 stages (Cs 128x132 f32 aliases)

__device__ __forceinline__ uint32_t swadr(uint32_t base, int row, int c16) {
    return base + row * 128 + ((c16 ^ (row & 7)) << 4);
}

template <int EPI>
__global__ void __launch_bounds__(256, 2)
gemm_mma(const __half* __restrict__ Ag, const __half* __restrict__ Bg,
         int K, int KB, int Mreal,
         float* __restrict__ outf, int ldo,
         __half* __restrict__ oh, int ldob,
         const float* __restrict__ sv, const float* __restrict__ tv,
         const float* __restrict__ rs,
         const __half* __restrict__ r16,
         const float* __restrict__ watt) {
    extern __shared__ __half smbuf[];
    const uint32_t sb = smem_u32(smbuf);
    const int tid = threadIdx.x, lane = tid & 31, wid = tid >> 5;
    const int mt = blockIdx.x, nt = blockIdx.y;
    const int wm = (wid & 3) * 32, wn = (wid >> 2) * 64;

    float acc[2][8][4];
#pragma unroll
    for (int a = 0; a < 2; a++)
#pragma unroll
        for (int b = 0; b < 8; b++)
#pragma unroll
            for (int c = 0; c < 4; c++) acc[a][b][c] = 0.f;

    auto load_stage = [&](int s, int kb) {
        uint32_t dstb = sb + s * STG;
        int k0 = kb * 64;
#pragma unroll
        for (int c = 0; c < 4; c++) {
            int q = tid + c * 256;
            int r = q >> 3, ch = q & 7;
            uint32_t d = dstb + r * 128 + ((ch ^ (r & 7)) << 4);
            size_t offA = (size_t)(mt * 128 + r) * K + k0 + ch * 8;
            size_t offB = (size_t)(nt * 128 + r) * K + k0 + ch * 8;
            cp16(d,       Ag + offA);
            cp16(d + TIL, Bg + offB);
        }
    };

    const int grp = lane >> 3, lrow = lane & 7;

    auto compute_stage = [&](int s) {
        uint32_t base = sb + s * STG;
#pragma unroll
        for (int ks2 = 0; ks2 < 4; ks2++) {
            uint32_t ah[2][4], bf[8][2];
            const int cA = ks2 * 2 + (grp >> 1);
            const int cB = ks2 * 2 + (grp & 1);
#pragma unroll
            for (int mi = 0; mi < 2; mi++) {
                int row = wm + mi * 16 + (grp & 1) * 8 + lrow;
                ldsm_x4(ah[mi], swadr(base, row, cA));
            }
#pragma unroll
            for (int n2 = 0; n2 < 4; n2++) {
                int row = wn + n2 * 16 + (grp >> 1) * 8 + lrow;
                uint32_t q[4];
                ldsm_x4(q, swadr(base + TIL, row, cB));
                bf[n2 * 2][0] = q[0]; bf[n2 * 2][1] = q[1];
                bf[n2 * 2 + 1][0] = q[2]; bf[n2 * 2 + 1][1] = q[3];
            }
#pragma unroll
            for (int mi = 0; mi < 2; mi++)
#pragma unroll
                for (int ni = 0; ni < 8; ni++) mma_f16(acc[mi][ni], ah[mi], bf[ni]);
        }
    };

    load_stage(0, 0); CP_COMMIT();
    if (KB > 1) { load_stage(1, 1); CP_COMMIT(); }
    for (int kb = 0; kb < KB; kb++) {
        if (kb + 1 < KB) { CP_WAIT(1); } else { CP_WAIT(0); }
        __syncthreads();
        if (kb + 2 < KB) { load_stage((kb + 2) % 3, kb + 2); CP_COMMIT(); }
        compute_stage(kb % 3);
    }
    __syncthreads();

    float* Cs = reinterpret_cast<float*>(smbuf);
#pragma unroll
    for (int mi = 0; mi < 2; mi++)
#pragma unroll
        for (int ni = 0; ni < 8; ni++) {
            int rm = wm + mi * 16 + (lane >> 2);
            int cn = wn + ni * 8 + 2 * (lane & 3);
            Cs[cn * 132 + rm]           = acc[mi][ni][0];
            Cs[(cn + 1) * 132 + rm]     = acc[mi][ni][1];
            Cs[cn * 132 + rm + 8]       = acc[mi][ni][2];
            Cs[(cn + 1) * 132 + rm + 8] = acc[mi][ni][3];
        }
    __syncthreads();

    {
        int nl = tid >> 1, m0 = (tid & 1) * 64;
        int ng = nt * 128 + nl;
        int mg0 = mt * 128 + m0;
        if constexpr (EPI == 6) {
            if (mg0 < 1088) {  // ag half: relu -> fp16 G
#pragma unroll
                for (int j0 = 0; j0 < 64; j0 += 8) {
                    union { __half h[8]; uint4 v; } ph;
#pragma unroll
                    for (int e = 0; e < 8; e++) {
                        int m = mg0 + j0 + e;
                        float v = Cs[nl * 132 + m0 + j0 + e] * rs[m];
                        ph.h[e] = __float2half(fmaxf(fmaf(sv[m], v, tv[m]), 0.f));
                    }
                    *reinterpret_cast<uint4*>(oh + (size_t)ng * ldob + mg0 + j0) = ph.v;
                }
            } else {  // att half: fused logit dot
                float wsum = 0.f;
#pragma unroll 8
                for (int j = 0; j < 64; j++) {
                    int m = mg0 + j;
                    float v = Cs[nl * 132 + m0 + j] * rs[m];
                    wsum = fmaf(fmaxf(fmaf(sv[m], v, tv[m]), 0.f), watt[m], wsum);
                }
                atomicAdd(&outf[ng], wsum);
            }
        } else if constexpr (EPI == 2 || EPI == 3) {
#pragma unroll
            for (int j0 = 0; j0 < 64; j0 += 8) {
                if (mg0 + j0 >= Mreal) break;
                union { __half h[8]; uint4 v; } ph;
                float rv[8];
                if constexpr (EPI == 3) {
                    uint4 r4 = *reinterpret_cast<const uint4*>(r16 + (size_t)ng * ldob + mg0 + j0);
                    const __half* rr = reinterpret_cast<const __half*>(&r4);
#pragma unroll
                    for (int e = 0; e < 8; e++) rv[e] = __half2float(rr[e]);
                }
#pragma unroll
                for (int e = 0; e < 8; e++) {
                    int m = mg0 + j0 + e;
                    float v = Cs[nl * 132 + m0 + j0 + e] * rs[m];
                    float w = fmaxf(fmaf(sv[m], v, tv[m]), 0.f);
                    if constexpr (EPI == 3) w += rv[e];
                    ph.h[e] = __float2half(w);
                }
                *reinterpret_cast<uint4*>(oh + (size_t)ng * ldob + mg0 + j0) = ph.v;
            }
        } else {
#pragma unroll
            for (int j0 = 0; j0 < 64; j0 += 4) {
                if (mg0 + j0 >= Mreal) break;
                float4 ov;
                float* pv = reinterpret_cast<float*>(&ov);
#pragma unroll
                for (int e = 0; e < 4; e++) {
                    int m = mg0 + j0 + e;
                    float v = Cs[nl * 132 + m0 + j0 + e] * rs[m];
                    if constexpr (EPI == 4) v = v + sv[m];
                    pv[e] = v;
                }
                *reinterpret_cast<float4*>(outf + (size_t)ng * ldo + mg0 + j0) = ov;
            }
        }
    }
}

// ---------------- launch ----------------
extern "C" void kernel_launch(void* const* d_in, const int* in_sizes, int n_in,
                              void* d_out, int out_size) {
    const float *x = (const float*)d_in[0], *pos2d = (const float*)d_in[1];
    const float *w_pos = (const float*)d_in[2], *b_pos = (const float*)d_in[3];
    const float *w_e = (const float*)d_in[4],  *w1 = (const float*)d_in[6];
    const float *w2 = (const float*)d_in[8],   *w_ag = (const float*)d_in[10];
    const float *w_ag_s = (const float*)d_in[12], *b_ag_s = (const float*)d_in[13];
    const float *w_att = (const float*)d_in[14], *w_att_s = (const float*)d_in[16];
    const float *b_att_s = (const float*)d_in[17], *Wsm = (const float*)d_in[18];
    float* out = (float*)d_out;

    float* F32 = nullptr;  __half* H16 = nullptr;
    cudaGetSymbolAddress((void**)&F32, g_F32);
    cudaGetSymbolAddress((void**)&H16, g_H16);

    float *F = F32+OF_F, *P2 = F32+OF_P2, *WPT = F32+OF_WPT, *PP = F32+OF_PP;
    float *AB = F32+OF_AB, *AG = F32+OF_AG, *FST = F32+OF_FST;
    float *ATTL = F32+OF_ATTL, *ATTS = F32+OF_ATTS, *SBN = F32+OF_SBN;
    float *RSWE = F32+OF_RSWE, *RSW1 = F32+OF_RSW1, *RSW2 = F32+OF_RSW2;
    float *RSGA = F32+OF_RSGA, *RSWS = F32+OF_RSWS, *RS01 = F32+OF_RS01;
    float *S6 = F32+OF_S6, *T6 = F32+OF_T6, *WT2 = F32+OF_WT2;

    cudaFuncSetAttribute(gemm_mma<0>, cudaFuncAttributeMaxDynamicSharedMemorySize, SMEMB);
    cudaFuncSetAttribute(gemm_mma<2>, cudaFuncAttributeMaxDynamicSharedMemorySize, SMEMB);
    cudaFuncSetAttribute(gemm_mma<3>, cudaFuncAttributeMaxDynamicSharedMemorySize, SMEMB);
    cudaFuncSetAttribute(gemm_mma<4>, cudaFuncAttributeMaxDynamicSharedMemorySize, SMEMB);
    cudaFuncSetAttribute(gemm_mma<6>, cudaFuncAttributeMaxDynamicSharedMemorySize, SMEMB);

    // launches 1-3, big layer-1 GEMM at slot 4 (ncu captures the 4th launch)
    k_build_f<<<(P4_*72+255)/256, 256>>>(x, F, H16+OB_FB);
    k_wsp<<<(2176+7)/8, 256>>>(w_e, nullptr, 0, 2176, 544, KP5, 2176, 3, RSWE, H16+OB_WE);
    k_bn_fold<<<(5*CIN_+255)/256, 256>>>((const float*)d_in[5], (const float*)d_in[7],
                                         (const float*)d_in[9], (const float*)d_in[11],
                                         (const float*)d_in[15], SBN);
    gemm_mma<0><<<dim3(17,32),256,SMEMB>>>(H16+OB_WE, H16+OB_FB,
                                           KP5, 9, 2176, AB, 2176, nullptr, 0,
                                           nullptr, nullptr, RSWE, nullptr, nullptr);

    k_wposT<<<(PCH_*CIN_+255)/256, 256>>>(w_pos, WPT);
    k_build_p<<<(P4_*PCH_+255)/256, 256>>>(pos2d, P2);
    k_pos<<<(P4_*CIN_+255)/256, 256>>>(WPT, P2, PP);
    k_h0<<<(P16_*136+255)/256, 256>>>(AB, PP, b_pos, SBN, H16+OB_H0);

    // fused weight preps (6 launches)
    k_wsp<<<(1152+7)/8, 256>>>(w1,    nullptr, CIN_, 1088, 1088, 1088, 1152, 0, RSW1, H16+OB_W1);
    k_wsp<<<(1152+7)/8, 256>>>(w2,    nullptr, CIN_, 1088, 1088, 1088, 1152, 0, RSW2, H16+OB_W2);
    k_wsp<<<(2176+7)/8, 256>>>(w_ag,  w_att,   CIN_, 2176, 1088, 1088, 2176, 5, RSGA, H16+OB_WGA);
    k_wsp<<<(640+7)/8, 256>>>(w_ag_s, nullptr, CIN_, 544, 1088, 1088, 640, 0, RSWS, H16+OB_WS);
    k_wsp<<<(1152+7)/8, 256>>>(Wsm,   nullptr, 0, 1088, 544, KP5, 1152, 2, RS01, H16+OB_W01);
    k_combine<<<(2176+255)/256, 256>>>(SBN, w_att_s, S6, T6, WT2);

    // trunk
    gemm_mma<2><<<dim3(9,128),256,SMEMB>>>(H16+OB_W1, H16+OB_H0,
                                           1088, 17, 1088, nullptr, 0, H16+OB_H1, CIN_,
                                           SBN+2*CIN_, SBN+3*CIN_, RSW1, nullptr, nullptr);
    gemm_mma<3><<<dim3(9,128),256,SMEMB>>>(H16+OB_W2, H16+OB_H1,
                                           1088, 17, 1088, nullptr, 0, H16+OB_H2, CIN_,
                                           SBN+4*CIN_, SBN+5*CIN_, RSW2, H16+OB_H0, nullptr);
    // merged ag+att stacked GEMM (hybrid epilogue)
    k_attl_init<<<(P16_+255)/256, 256>>>(b_att_s, ATTL);
    gemm_mma<6><<<dim3(17,128),256,SMEMB>>>(H16+OB_WGA, H16+OB_H2,
                                            1088, 17, 2176, ATTL, 0, H16+OB_G, CIN_,
                                            S6, T6, RSGA, nullptr, WT2);
    // ag_s GEMM + softmax
    gemm_mma<4><<<dim3(5,128),256,SMEMB>>>(H16+OB_WS, H16+OB_G,
                                           1088, 17, 544, AG, C_, nullptr, 0,
                                           b_ag_s, nullptr, RSWS, nullptr, nullptr);
    k_softmax<<<(P4_+255)/256, 256>>>(ATTL, ATTS);

    // self/transfer stacked: FST = [W0^T; W1^T] @ f
    gemm_mma<0><<<dim3(9,32),256,SMEMB>>>(H16+OB_W01, H16+OB_FB,
                                          KP5, 9, 1088, FST, CIN_, nullptr, 0,
                                          nullptr, nullptr, RS01, nullptr, nullptr);

    k_fuse<<<(BT_*2176+255)/256, 256>>>(F, FST, AG, ATTS, out);
}